// round 1
// baseline (speedup 1.0000x reference)
#include <cuda_runtime.h>
#include <math.h>

#define Bdim 2
#define Tdim 2048
#define Cdim 768
#define Hdim 12
#define Ddim 64
#define Ldim 6
#define Vdim 50257
#define Mdim (Bdim*Tdim)      /* 4096 rows of tokens */
#define C3   (3*Cdim)         /* 2304 */
#define Fdim (4*Cdim)         /* 3072 */

// ---------------- scratch (static device globals; no allocations) ----------
__device__ float g_h  [Mdim*Cdim];                 // 12.6 MB residual stream
__device__ float g_xn [Mdim*Cdim];                 // 12.6 MB layernorm out
__device__ float g_qkv[Mdim*C3];                   // 37.7 MB
__device__ float g_ffh[Mdim*Fdim];                 // 50 MB
__device__ float g_att[Bdim*Hdim*Tdim*Tdim];       // 402 MB attention probs
__device__ float g_rowloss[Mdim];

// ---------------- block reductions (256 threads) ---------------------------
__device__ __forceinline__ float blockReduceMax(float v){
    __shared__ float sh[8];
    int lid = threadIdx.x & 31, wid = threadIdx.x >> 5;
    #pragma unroll
    for (int o = 16; o > 0; o >>= 1) v = fmaxf(v, __shfl_xor_sync(0xffffffffu, v, o));
    if (lid == 0) sh[wid] = v;
    __syncthreads();
    v = sh[lid & 7];
    #pragma unroll
    for (int o = 4; o > 0; o >>= 1) v = fmaxf(v, __shfl_xor_sync(0xffffffffu, v, o));
    __syncthreads();
    return v;
}
__device__ __forceinline__ float blockReduceSum(float v){
    __shared__ float sh[8];
    int lid = threadIdx.x & 31, wid = threadIdx.x >> 5;
    #pragma unroll
    for (int o = 16; o > 0; o >>= 1) v += __shfl_xor_sync(0xffffffffu, v, o);
    if (lid == 0) sh[wid] = v;
    __syncthreads();
    v = sh[lid & 7];
    #pragma unroll
    for (int o = 4; o > 0; o >>= 1) v += __shfl_xor_sync(0xffffffffu, v, o);
    __syncthreads();
    return v;
}

// ---------------- embedding -------------------------------------------------
__global__ void embed_k(const int* __restrict__ x,
                        const float* __restrict__ wte,
                        const float* __restrict__ wpe){
    int i = blockIdx.x * blockDim.x + threadIdx.x;
    if (i >= Mdim * Cdim) return;
    int c  = i % Cdim;
    int bt = i / Cdim;
    int t  = bt % Tdim;
    g_h[i] = wte[(size_t)x[bt] * Cdim + c] + wpe[(size_t)t * Cdim + c];
}

// ---------------- layernorm (one block of 256 per row, C=768) ---------------
__global__ void ln_k(const float* __restrict__ in,
                     const float* __restrict__ w,
                     const float* __restrict__ b,
                     float* __restrict__ out){
    int row = blockIdx.x, tid = threadIdx.x;
    const float* xp = in + (size_t)row * Cdim;
    float v[3], s = 0.f, ss = 0.f;
    #pragma unroll
    for (int i = 0; i < 3; i++){
        v[i] = xp[tid + i * 256];
        s += v[i]; ss += v[i] * v[i];
    }
    s  = blockReduceSum(s);
    ss = blockReduceSum(ss);
    float mean = s * (1.f / Cdim);
    float var  = ss * (1.f / Cdim) - mean * mean;
    float rstd = rsqrtf(var + 1e-5f);
    float* op = out + (size_t)row * Cdim;
    #pragma unroll
    for (int i = 0; i < 3; i++){
        int c = tid + i * 256;
        op[c] = (v[i] - mean) * rstd * w[c] + b[c];
    }
}

// ---------------- SGEMM: C[M,N] = A[M,K] @ B[N,K]^T (+bias,+res,relu) -------
// 128x128x8 tile, 256 threads, 8x8 register tile per thread.
__global__ __launch_bounds__(256) void gemm_nt_k(
        const float* __restrict__ A, const float* __restrict__ Bm,
        const float* __restrict__ bias, const float* __restrict__ res,
        float* __restrict__ Co, int N, int K, int ldc, int relu){
    __shared__ float As[8][128];
    __shared__ float Bs[8][128];
    int tid = threadIdx.x;
    int bx = blockIdx.x, by = blockIdx.y;
    int tx = tid % 16, ty = tid / 16;

    int aRow = tid >> 1;            // 0..127
    int aCol = (tid & 1) * 4;       // 0 or 4
    int gARow = by * 128 + aRow;
    int gBRow = bx * 128 + aRow;
    bool bvalid = (gBRow < N);
    const float* Aptr = A  + (size_t)gARow * K + aCol;
    const float* Bptr = Bm + (size_t)(bvalid ? gBRow : 0) * K + aCol;

    float acc[8][8] = {};
    for (int k0 = 0; k0 < K; k0 += 8){
        float4 av = *(const float4*)(Aptr + k0);
        float4 bv = bvalid ? *(const float4*)(Bptr + k0) : make_float4(0.f,0.f,0.f,0.f);
        As[aCol+0][aRow] = av.x; As[aCol+1][aRow] = av.y;
        As[aCol+2][aRow] = av.z; As[aCol+3][aRow] = av.w;
        Bs[aCol+0][aRow] = bv.x; Bs[aCol+1][aRow] = bv.y;
        Bs[aCol+2][aRow] = bv.z; Bs[aCol+3][aRow] = bv.w;
        __syncthreads();
        #pragma unroll
        for (int kk = 0; kk < 8; kk++){
            float a[8], bb[8];
            *(float4*)(a)   = *(const float4*)&As[kk][ty*8];
            *(float4*)(a+4) = *(const float4*)&As[kk][ty*8+4];
            *(float4*)(bb)  = *(const float4*)&Bs[kk][tx*8];
            *(float4*)(bb+4)= *(const float4*)&Bs[kk][tx*8+4];
            #pragma unroll
            for (int i = 0; i < 8; i++)
                #pragma unroll
                for (int j = 0; j < 8; j++)
                    acc[i][j] += a[i] * bb[j];
        }
        __syncthreads();
    }

    #pragma unroll
    for (int i = 0; i < 8; i++){
        int r = by * 128 + ty * 8 + i;
        #pragma unroll
        for (int j = 0; j < 8; j++){
            int c = bx * 128 + tx * 8 + j;
            if (c < N){
                float vv = acc[i][j];
                if (bias) vv += bias[c];
                if (res)  vv += res[(size_t)r * N + c];
                if (relu) vv = fmaxf(vv, 0.f);
                Co[(size_t)r * ldc + c] = vv;
            }
        }
    }
}

// ---------------- attention scores: att[bh,t,s] = scale * q.k (s<=t only) ---
__global__ __launch_bounds__(256) void attn_scores_k(){
    int bh = blockIdx.z; int bq = bh / Hdim; int head = bh % Hdim;
    int t0 = blockIdx.y * 64, s0 = blockIdx.x * 64;
    if (s0 > t0 + 63) return;                 // fully masked tile
    __shared__ float Qs[16][64];
    __shared__ float Ks[16][64];
    int tid = threadIdx.x, tx = tid % 16, ty = tid / 16;
    int lr = tid / 4;                          // 0..63
    int lc = (tid % 4) * 4;                    // 0,4,8,12
    const float* qbase = g_qkv + (size_t)(bq*Tdim + t0 + lr)*C3 + head*Ddim + lc;
    const float* kbase = g_qkv + (size_t)(bq*Tdim + s0 + lr)*C3 + Cdim + head*Ddim + lc;

    float acc[4][4] = {};
    for (int d0 = 0; d0 < Ddim; d0 += 16){
        float4 qv = *(const float4*)(qbase + d0);
        float4 kv = *(const float4*)(kbase + d0);
        Qs[lc+0][lr]=qv.x; Qs[lc+1][lr]=qv.y; Qs[lc+2][lr]=qv.z; Qs[lc+3][lr]=qv.w;
        Ks[lc+0][lr]=kv.x; Ks[lc+1][lr]=kv.y; Ks[lc+2][lr]=kv.z; Ks[lc+3][lr]=kv.w;
        __syncthreads();
        #pragma unroll
        for (int kk = 0; kk < 16; kk++){
            float a[4], b[4];
            *(float4*)a = *(const float4*)&Qs[kk][ty*4];
            *(float4*)b = *(const float4*)&Ks[kk][tx*4];
            #pragma unroll
            for (int i = 0; i < 4; i++)
                #pragma unroll
                for (int j = 0; j < 4; j++)
                    acc[i][j] += a[i] * b[j];
        }
        __syncthreads();
    }
    const float scale = 0.125f;               // 1/sqrt(64)
    #pragma unroll
    for (int i = 0; i < 4; i++){
        int t = t0 + ty*4 + i;
        #pragma unroll
        for (int j = 0; j < 4; j++){
            int s = s0 + tx*4 + j;
            if (s <= t)
                g_att[(size_t)bh*Tdim*Tdim + (size_t)t*Tdim + s] = acc[i][j]*scale;
        }
    }
}

// ---------------- causal softmax over row [0..t]; zeros for s>t -------------
__global__ void softmax_k(){
    int row = blockIdx.x;                      // bh*T + t
    int t = row % Tdim;
    float* p = g_att + (size_t)row * Tdim;
    int n = t + 1;
    int tid = threadIdx.x;
    float m = -1e30f;
    for (int i = tid; i < n; i += 256) m = fmaxf(m, p[i]);
    m = blockReduceMax(m);
    float s = 0.f;
    for (int i = tid; i < n; i += 256) s += __expf(p[i] - m);
    s = blockReduceSum(s);
    float inv = 1.f / s;
    for (int i = tid; i < Tdim; i += 256)
        p[i] = (i < n) ? __expf(p[i] - m) * inv : 0.f;
}

// ---------------- y = att @ V ; h += y --------------------------------------
__global__ __launch_bounds__(256) void attn_av_k(){
    int bh = blockIdx.y; int bq = bh / Hdim, head = bh % Hdim;
    int t0 = blockIdx.x * 64;
    __shared__ float Ats[64][64];
    __shared__ float Vs [64][64];
    int tid = threadIdx.x, tx = tid % 16, ty = tid / 16;

    float acc[4][4] = {};
    int smax = t0 + 63;
    for (int s0 = 0; s0 <= smax; s0 += 64){
        #pragma unroll
        for (int k = 0; k < 4; k++){
            int vi = tid + k * 256;
            int r = vi >> 4, c4 = (vi & 15) * 4;
            *(float4*)&Ats[r][c4] =
                *(const float4*)(g_att + (size_t)bh*Tdim*Tdim + (size_t)(t0+r)*Tdim + s0 + c4);
            *(float4*)&Vs[r][c4] =
                *(const float4*)(g_qkv + (size_t)(bq*Tdim + s0 + r)*C3 + 2*Cdim + head*Ddim + c4);
        }
        __syncthreads();
        #pragma unroll
        for (int kk = 0; kk < 64; kk++){
            float a[4], b[4];
            #pragma unroll
            for (int i = 0; i < 4; i++) a[i] = Ats[ty*4+i][kk];
            *(float4*)b = *(const float4*)&Vs[kk][tx*4];
            #pragma unroll
            for (int i = 0; i < 4; i++)
                #pragma unroll
                for (int j = 0; j < 4; j++)
                    acc[i][j] += a[i] * b[j];
        }
        __syncthreads();
    }
    #pragma unroll
    for (int i = 0; i < 4; i++){
        int t = t0 + ty*4 + i;
        float* hp = g_h + (size_t)(bq*Tdim + t)*Cdim + head*Ddim + tx*4;
        #pragma unroll
        for (int j = 0; j < 4; j++) hp[j] += acc[i][j];
    }
}

// ---------------- cross-entropy ---------------------------------------------
__global__ void loss_row_k(const float* __restrict__ logits,
                           const int* __restrict__ target){
    int row = blockIdx.x, tid = threadIdx.x;
    const float* p = logits + (size_t)row * Vdim;
    float m = -1e30f;
    for (int i = tid; i < Vdim; i += 256) m = fmaxf(m, p[i]);
    m = blockReduceMax(m);
    float s = 0.f;
    for (int i = tid; i < Vdim; i += 256) s += __expf(p[i] - m);
    s = blockReduceSum(s);
    if (tid == 0){
        float lse = logf(s) + m;
        g_rowloss[row] = lse - p[target[row]];
    }
}
__global__ void loss_reduce_k(float* out){
    float s = 0.f;
    for (int i = threadIdx.x; i < Mdim; i += 256) s += g_rowloss[i];
    s = blockReduceSum(s);
    if (threadIdx.x == 0) out[0] = s / (float)Mdim;
}

// ---------------- launch ----------------------------------------------------
extern "C" void kernel_launch(void* const* d_in, const int* in_sizes, int n_in,
                              void* d_out, int out_size){
    const int*   x      = (const int*)  d_in[0];
    const int*   target = (const int*)  d_in[1];
    const float* wte    = (const float*)d_in[2];
    const float* wpe    = (const float*)d_in[3];
    const float* ln1_w  = (const float*)d_in[4];
    const float* ln1_b  = (const float*)d_in[5];
    const float* attn_w = (const float*)d_in[6];
    const float* attn_b = (const float*)d_in[7];
    const float* ln2_w  = (const float*)d_in[8];
    const float* ln2_b  = (const float*)d_in[9];
    const float* ff1_w  = (const float*)d_in[10];
    const float* ff1_b  = (const float*)d_in[11];
    const float* ff2_w  = (const float*)d_in[12];
    const float* ff2_b  = (const float*)d_in[13];
    const float* lm_w   = (const float*)d_in[14];

    float* out = (float*)d_out;
    bool has_loss = ((long long)out_size == (long long)Mdim * Vdim + 1);
    float* logits = has_loss ? out + 1 : out;

    float *ph, *pxn, *pqkv, *pffh;
    cudaGetSymbolAddress((void**)&ph,   g_h);
    cudaGetSymbolAddress((void**)&pxn,  g_xn);
    cudaGetSymbolAddress((void**)&pqkv, g_qkv);
    cudaGetSymbolAddress((void**)&pffh, g_ffh);

    embed_k<<<(Mdim*Cdim + 255)/256, 256>>>(x, wte, wpe);

    for (int l = 0; l < Ldim; l++){
        ln_k<<<Mdim, 256>>>(ph, ln1_w + (size_t)l*Cdim, ln1_b + (size_t)l*Cdim, pxn);

        gemm_nt_k<<<dim3(C3/128, Mdim/128), 256>>>(
            pxn, attn_w + (size_t)l*C3*Cdim, attn_b + (size_t)l*C3,
            nullptr, pqkv, C3, Cdim, C3, 0);

        attn_scores_k<<<dim3(Tdim/64, Tdim/64, Bdim*Hdim), 256>>>();
        softmax_k<<<Bdim*Hdim*Tdim, 256>>>();
        attn_av_k<<<dim3(Tdim/64, Bdim*Hdim), 256>>>();

        ln_k<<<Mdim, 256>>>(ph, ln2_w + (size_t)l*Cdim, ln2_b + (size_t)l*Cdim, pxn);

        gemm_nt_k<<<dim3(Fdim/128, Mdim/128), 256>>>(
            pxn, ff1_w + (size_t)l*Fdim*Cdim, ff1_b + (size_t)l*Fdim,
            nullptr, pffh, Fdim, Cdim, Fdim, 1);

        gemm_nt_k<<<dim3(Cdim/128, Mdim/128), 256>>>(
            pffh, ff2_w + (size_t)l*Cdim*Fdim, ff2_b + (size_t)l*Cdim,
            ph, ph, Cdim, Fdim, Cdim, 0);
    }

    gemm_nt_k<<<dim3((Vdim + 127)/128, Mdim/128), 256>>>(
        ph, lm_w, nullptr, nullptr, logits, Vdim, Cdim, Vdim, 0);

    loss_row_k<<<Mdim, 256>>>(logits, target);
    if (has_loss)
        loss_reduce_k<<<1, 256>>>(out);
}

// round 3
// speedup vs baseline: 1.8611x; 1.8611x over previous
#include <cuda_runtime.h>
#include <cuda_bf16.h>
#include <cstdint>
#include <math.h>

#define Bdim 2
#define Tdim 2048
#define Cdim 768
#define Hdim 12
#define Ddim 64
#define Ldim 6
#define Vdim 50257
#define Mdim (Bdim*Tdim)      /* 4096 */
#define C3   (3*Cdim)         /* 2304 */
#define Fdim (4*Cdim)         /* 3072 */

// ===================== device scratch (no allocations) ======================
__device__ float g_h  [Mdim*Cdim];
__device__ float g_qkv[Mdim*C3];
__device__ float g_att[Bdim*Hdim*Tdim*Tdim];
__device__ float g_rowloss[Mdim];

__device__ __nv_bfloat16 g_wqkv_hi[Ldim*C3*Cdim],  g_wqkv_lo[Ldim*C3*Cdim];
__device__ __nv_bfloat16 g_wff1_hi[Ldim*Fdim*Cdim], g_wff1_lo[Ldim*Fdim*Cdim];
__device__ __nv_bfloat16 g_wff2_hi[Ldim*Cdim*Fdim], g_wff2_lo[Ldim*Cdim*Fdim];
__device__ __nv_bfloat16 g_wlm_hi[(size_t)Vdim*Cdim], g_wlm_lo[(size_t)Vdim*Cdim];
__device__ __nv_bfloat16 g_xn_hi[Mdim*Cdim],  g_xn_lo[Mdim*Cdim];
__device__ __nv_bfloat16 g_ffh_hi[Mdim*Fdim], g_ffh_lo[Mdim*Fdim];
__device__ __nv_bfloat16 g_ah_hi[Mdim*Cdim],  g_ah_lo[Mdim*Cdim];

// ===================== asm helpers (baseline sm_80+ ISA) ====================
__device__ __forceinline__ uint32_t smem_to_u32(const void* p) {
    uint32_t a;
    asm("{ .reg .u64 t; cvta.to.shared.u64 t, %1; cvt.u32.u64 %0, t; }" : "=r"(a) : "l"(p));
    return a;
}
__device__ __forceinline__ void cp_async16(uint32_t dst, const void* src){
    asm volatile("cp.async.cg.shared.global [%0], [%1], 16;" :: "r"(dst), "l"(src));
}
#define CP_COMMIT() asm volatile("cp.async.commit_group;" ::: "memory")
#define CP_WAIT1()  asm volatile("cp.async.wait_group 1;" ::: "memory")
#define CP_WAIT0()  asm volatile("cp.async.wait_group 0;" ::: "memory")

__device__ __forceinline__ void ldsm_x4(uint32_t* r, uint32_t addr){
    asm volatile("ldmatrix.sync.aligned.m8n8.x4.shared.b16 {%0,%1,%2,%3}, [%4];"
        : "=r"(r[0]), "=r"(r[1]), "=r"(r[2]), "=r"(r[3]) : "r"(addr));
}
__device__ __forceinline__ void mma_bf16(float* d, const uint32_t* a,
                                         uint32_t b0, uint32_t b1){
    asm volatile("mma.sync.aligned.m16n8k16.row.col.f32.bf16.bf16.f32 "
        "{%0,%1,%2,%3}, {%4,%5,%6,%7}, {%8,%9}, {%0,%1,%2,%3};"
        : "+f"(d[0]), "+f"(d[1]), "+f"(d[2]), "+f"(d[3])
        : "r"(a[0]), "r"(a[1]), "r"(a[2]), "r"(a[3]), "r"(b0), "r"(b1));
}

// ===================== reductions ===========================================
__device__ __forceinline__ float blockReduceMax(float v){
    __shared__ float sh[8];
    int lid = threadIdx.x & 31, wid = threadIdx.x >> 5;
    #pragma unroll
    for (int o = 16; o > 0; o >>= 1) v = fmaxf(v, __shfl_xor_sync(0xffffffffu, v, o));
    if (lid == 0) sh[wid] = v;
    __syncthreads();
    v = sh[lid & 7];
    #pragma unroll
    for (int o = 4; o > 0; o >>= 1) v = fmaxf(v, __shfl_xor_sync(0xffffffffu, v, o));
    __syncthreads();
    return v;
}
__device__ __forceinline__ float blockReduceSum(float v){
    __shared__ float sh[8];
    int lid = threadIdx.x & 31, wid = threadIdx.x >> 5;
    #pragma unroll
    for (int o = 16; o > 0; o >>= 1) v += __shfl_xor_sync(0xffffffffu, v, o);
    if (lid == 0) sh[wid] = v;
    __syncthreads();
    v = sh[lid & 7];
    #pragma unroll
    for (int o = 4; o > 0; o >>= 1) v += __shfl_xor_sync(0xffffffffu, v, o);
    __syncthreads();
    return v;
}

// ===================== small kernels ========================================
__global__ void embed_k(const int* __restrict__ x,
                        const float* __restrict__ wte,
                        const float* __restrict__ wpe){
    int i = blockIdx.x * blockDim.x + threadIdx.x;
    if (i >= Mdim * Cdim) return;
    int c  = i % Cdim;
    int bt = i / Cdim;
    int t  = bt % Tdim;
    g_h[i] = wte[(size_t)x[bt] * Cdim + c] + wpe[(size_t)t * Cdim + c];
}

__global__ void cvt_k(const float* __restrict__ in, __nv_bfloat16* __restrict__ hi,
                      __nv_bfloat16* __restrict__ lo, long n){
    long stride = (long)gridDim.x * blockDim.x;
    for (long i = blockIdx.x * (long)blockDim.x + threadIdx.x; i < n; i += stride){
        float v = in[i];
        __nv_bfloat16 h = __float2bfloat16(v);
        hi[i] = h;
        lo[i] = __float2bfloat16(v - __bfloat162float(h));
    }
}

__global__ void ln_k(const float* __restrict__ in,
                     const float* __restrict__ w,
                     const float* __restrict__ b,
                     __nv_bfloat16* __restrict__ ohi,
                     __nv_bfloat16* __restrict__ olo){
    int row = blockIdx.x, tid = threadIdx.x;
    const float* xp = in + (size_t)row * Cdim;
    float v[3], s = 0.f, ss = 0.f;
    #pragma unroll
    for (int i = 0; i < 3; i++){
        v[i] = xp[tid + i * 256];
        s += v[i]; ss += v[i] * v[i];
    }
    s  = blockReduceSum(s);
    ss = blockReduceSum(ss);
    float mean = s * (1.f / Cdim);
    float var  = ss * (1.f / Cdim) - mean * mean;
    float rstd = rsqrtf(var + 1e-5f);
    #pragma unroll
    for (int i = 0; i < 3; i++){
        int c = tid + i * 256;
        float y = (v[i] - mean) * rstd * w[c] + b[c];
        __nv_bfloat16 h = __float2bfloat16(y);
        ohi[(size_t)row * Cdim + c] = h;
        olo[(size_t)row * Cdim + c] = __float2bfloat16(y - __bfloat162float(h));
    }
}

// ===================== tensor-core split-bf16 GEMM (mma.sync) ===============
// C[M,N] = A[M,K] @ B[N,K]^T; A,B are (hi,lo) bf16 pairs; 3-term accumulate.
// CTA tile 128x128, 256 threads (8 warps, 2x4), warp tile 64x32.
// K staged 32 at a time, cp.async double buffered.
// modes: 0: out_f = acc+bias | 1: relu(acc+bias)->hi/lo | 2: out_f += acc+bias
//        3: out_f = acc
#define MAT_B   10240            /* 128 rows * 80 bytes */
#define STG_B   (4*MAT_B)        /* Ahi,Alo,Bhi,Blo     */
#define GT_SMEM (2*STG_B)        /* 81920 bytes         */

__global__ __launch_bounds__(256) void gemm_tc_k(
        const __nv_bfloat16* __restrict__ Ahi, const __nv_bfloat16* __restrict__ Alo,
        const __nv_bfloat16* __restrict__ Bhi, const __nv_bfloat16* __restrict__ Blo,
        const float* __restrict__ bias,
        float* __restrict__ out_f,
        __nv_bfloat16* __restrict__ out_hi, __nv_bfloat16* __restrict__ out_lo,
        int N, int K, int mode){
    extern __shared__ char smem[];
    uint32_t sbase = smem_to_u32(smem);
    int tid = threadIdx.x, wid = tid >> 5, lane = tid & 31;
    int warpRow = wid >> 2, warpCol = wid & 3;

    long row0 = (long)blockIdx.x * 128;
    long n0   = (long)blockIdx.y * 128;
    int nIter = K >> 5;

    float acc[4][4][4];
    #pragma unroll
    for (int i = 0; i < 4; i++)
        #pragma unroll
        for (int j = 0; j < 4; j++)
            #pragma unroll
            for (int q = 0; q < 4; q++) acc[i][j][q] = 0.f;

    // ---- stage loader: 2048 x 16B chunks, 8 per thread --------------------
    auto issue = [&](int it){
        if (it >= nIter) return;
        int k0 = it << 5;
        uint32_t stg = sbase + (uint32_t)(it & 1) * STG_B;
        #pragma unroll
        for (int j = 0; j < 8; j++){
            int c   = tid + j * 256;          // 0..2047
            int mat = c >> 9;                  // 0:Ahi 1:Alo 2:Bhi 3:Blo
            int id  = c & 511;
            int row = id >> 2;                 // 0..127
            int c8  = (id & 3) << 3;           // bf16 col 0,8,16,24
            const __nv_bfloat16* src;
            if (mat < 2){
                src = (mat == 0 ? Ahi : Alo) + (row0 + row) * (long)K + k0 + c8;
            } else {
                long br = n0 + row; if (br >= N) br = 0;
                src = (mat == 2 ? Bhi : Blo) + br * (long)K + k0 + c8;
            }
            uint32_t dst = stg + (uint32_t)(mat * MAT_B + row * 80 + c8 * 2);
            cp_async16(dst, src);
        }
        CP_COMMIT();
    };

    issue(0);
    for (int it = 0; it < nIter; it++){
        issue(it + 1);
        if (it + 1 < nIter) CP_WAIT1(); else CP_WAIT0();
        __syncthreads();

        uint32_t stg = sbase + (uint32_t)(it & 1) * STG_B;
        uint32_t aHi = stg;
        uint32_t aLo = stg + MAT_B;
        uint32_t bHi = stg + 2*MAT_B;
        uint32_t bLo = stg + 3*MAT_B;
        uint32_t rsel = (uint32_t)(lane & 15) * 80 + (uint32_t)(lane >> 4) * 16;

        #pragma unroll
        for (int ks = 0; ks < 32; ks += 16){
            uint32_t ah[4][4], al[4][4];
            #pragma unroll
            for (int mi = 0; mi < 4; mi++){
                uint32_t off = (uint32_t)((warpRow*64 + mi*16) * 80 + ks*2) + rsel;
                ldsm_x4(ah[mi], aHi + off);
                ldsm_x4(al[mi], aLo + off);
            }
            uint32_t bh[2][4], bl[2][4];
            #pragma unroll
            for (int nj = 0; nj < 2; nj++){
                uint32_t off = (uint32_t)((warpCol*32 + nj*16) * 80 + ks*2) + rsel;
                ldsm_x4(bh[nj], bHi + off);
                ldsm_x4(bl[nj], bLo + off);
            }
            #pragma unroll
            for (int mi = 0; mi < 4; mi++)
                #pragma unroll
                for (int ni = 0; ni < 4; ni++){
                    int nj = ni >> 1, w = ni & 1;
                    mma_bf16(acc[mi][ni], ah[mi], bh[nj][w], bh[nj][w+2]);
                    mma_bf16(acc[mi][ni], ah[mi], bl[nj][w], bl[nj][w+2]);
                    mma_bf16(acc[mi][ni], al[mi], bh[nj][w], bh[nj][w+2]);
                }
        }
        __syncthreads();
    }

    // ---- epilogue ---------------------------------------------------------
    #pragma unroll
    for (int mi = 0; mi < 4; mi++){
        long r0 = row0 + warpRow*64 + mi*16 + (lane >> 2);
        #pragma unroll
        for (int ni = 0; ni < 4; ni++){
            long c0 = n0 + warpCol*32 + ni*8 + (lane & 3)*2;
            #pragma unroll
            for (int half = 0; half < 2; half++){
                long r = r0 + half*8;
                #pragma unroll
                for (int e = 0; e < 2; e++){
                    long n = c0 + e;
                    if (n >= N) continue;
                    float v = acc[mi][ni][half*2 + e];
                    long oi = r * (long)N + n;
                    if (mode == 0){
                        out_f[oi] = v + bias[n];
                    } else if (mode == 1){
                        float y = fmaxf(v + bias[n], 0.f);
                        __nv_bfloat16 h = __float2bfloat16(y);
                        out_hi[oi] = h;
                        out_lo[oi] = __float2bfloat16(y - __bfloat162float(h));
                    } else if (mode == 2){
                        out_f[oi] += v + bias[n];
                    } else {
                        out_f[oi] = v;
                    }
                }
            }
        }
    }
}

// ===================== attention (fp32, from passing round-1) ===============
__global__ __launch_bounds__(256) void attn_scores_k(){
    int bh = blockIdx.z; int bq = bh / Hdim; int head = bh % Hdim;
    int t0 = blockIdx.y * 64, s0 = blockIdx.x * 64;
    if (s0 > t0 + 63) return;
    __shared__ float Qs[16][64];
    __shared__ float Ks[16][64];
    int tid = threadIdx.x, tx = tid % 16, ty = tid / 16;
    int lr = tid / 4;
    int lc = (tid % 4) * 4;
    const float* qbase = g_qkv + (size_t)(bq*Tdim + t0 + lr)*C3 + head*Ddim + lc;
    const float* kbase = g_qkv + (size_t)(bq*Tdim + s0 + lr)*C3 + Cdim + head*Ddim + lc;

    float acc[4][4] = {};
    for (int d0 = 0; d0 < Ddim; d0 += 16){
        float4 qv = *(const float4*)(qbase + d0);
        float4 kv = *(const float4*)(kbase + d0);
        Qs[lc+0][lr]=qv.x; Qs[lc+1][lr]=qv.y; Qs[lc+2][lr]=qv.z; Qs[lc+3][lr]=qv.w;
        Ks[lc+0][lr]=kv.x; Ks[lc+1][lr]=kv.y; Ks[lc+2][lr]=kv.z; Ks[lc+3][lr]=kv.w;
        __syncthreads();
        #pragma unroll
        for (int kk = 0; kk < 16; kk++){
            float a[4], b[4];
            *(float4*)a = *(const float4*)&Qs[kk][ty*4];
            *(float4*)b = *(const float4*)&Ks[kk][tx*4];
            #pragma unroll
            for (int i = 0; i < 4; i++)
                #pragma unroll
                for (int j = 0; j < 4; j++)
                    acc[i][j] += a[i] * b[j];
        }
        __syncthreads();
    }
    const float scale = 0.125f;
    #pragma unroll
    for (int i = 0; i < 4; i++){
        int t = t0 + ty*4 + i;
        #pragma unroll
        for (int j = 0; j < 4; j++){
            int s = s0 + tx*4 + j;
            if (s <= t)
                g_att[(size_t)bh*Tdim*Tdim + (size_t)t*Tdim + s] = acc[i][j]*scale;
        }
    }
}

__global__ void softmax_k(){
    int row = blockIdx.x;
    int t = row % Tdim;
    float* p = g_att + (size_t)row * Tdim;
    int n = t + 1;
    int tid = threadIdx.x;
    float m = -1e30f;
    for (int i = tid; i < n; i += 256) m = fmaxf(m, p[i]);
    m = blockReduceMax(m);
    float s = 0.f;
    for (int i = tid; i < n; i += 256) s += __expf(p[i] - m);
    s = blockReduceSum(s);
    float inv = 1.f / s;
    for (int i = tid; i < Tdim; i += 256)
        p[i] = (i < n) ? __expf(p[i] - m) * inv : 0.f;
}

__global__ __launch_bounds__(256) void attn_av_k(){
    int bh = blockIdx.y; int bq = bh / Hdim, head = bh % Hdim;
    int t0 = blockIdx.x * 64;
    __shared__ float Ats[64][64];
    __shared__ float Vs [64][64];
    int tid = threadIdx.x, tx = tid % 16, ty = tid / 16;

    float acc[4][4] = {};
    int smax = t0 + 63;
    for (int s0 = 0; s0 <= smax; s0 += 64){
        #pragma unroll
        for (int k = 0; k < 4; k++){
            int vi = tid + k * 256;
            int r = vi >> 4, c4 = (vi & 15) * 4;
            *(float4*)&Ats[r][c4] =
                *(const float4*)(g_att + (size_t)bh*Tdim*Tdim + (size_t)(t0+r)*Tdim + s0 + c4);
            *(float4*)&Vs[r][c4] =
                *(const float4*)(g_qkv + (size_t)(bq*Tdim + s0 + r)*C3 + 2*Cdim + head*Ddim + c4);
        }
        __syncthreads();
        #pragma unroll
        for (int kk = 0; kk < 64; kk++){
            float a[4], b[4];
            #pragma unroll
            for (int i = 0; i < 4; i++) a[i] = Ats[ty*4+i][kk];
            *(float4*)b = *(const float4*)&Vs[kk][tx*4];
            #pragma unroll
            for (int i = 0; i < 4; i++)
                #pragma unroll
                for (int j = 0; j < 4; j++)
                    acc[i][j] += a[i] * b[j];
        }
        __syncthreads();
    }
    #pragma unroll
    for (int i = 0; i < 4; i++){
        int t = t0 + ty*4 + i;
        float* hp = g_h + (size_t)(bq*Tdim + t)*Cdim + head*Ddim + tx*4;
        #pragma unroll
        for (int j = 0; j < 4; j++) hp[j] += acc[i][j];
    }
}

// ===================== cross-entropy ========================================
__global__ void loss_row_k(const float* __restrict__ logits,
                           const int* __restrict__ target){
    int row = blockIdx.x, tid = threadIdx.x;
    const float* p = logits + (size_t)row * Vdim;
    float m = -1e30f;
    for (int i = tid; i < Vdim; i += 256) m = fmaxf(m, p[i]);
    m = blockReduceMax(m);
    float s = 0.f;
    for (int i = tid; i < Vdim; i += 256) s += __expf(p[i] - m);
    s = blockReduceSum(s);
    if (tid == 0){
        float lse = logf(s) + m;
        g_rowloss[row] = lse - p[target[row]];
    }
}
__global__ void loss_reduce_k(float* out){
    float s = 0.f;
    for (int i = threadIdx.x; i < Mdim; i += 256) s += g_rowloss[i];
    s = blockReduceSum(s);
    if (threadIdx.x == 0) out[0] = s / (float)Mdim;
}

// ===================== launch ===============================================
extern "C" void kernel_launch(void* const* d_in, const int* in_sizes, int n_in,
                              void* d_out, int out_size){
    const int*   x      = (const int*)  d_in[0];
    const int*   target = (const int*)  d_in[1];
    const float* wte    = (const float*)d_in[2];
    const float* wpe    = (const float*)d_in[3];
    const float* ln1_w  = (const float*)d_in[4];
    const float* ln1_b  = (const float*)d_in[5];
    const float* attn_w = (const float*)d_in[6];
    const float* attn_b = (const float*)d_in[7];
    const float* ln2_w  = (const float*)d_in[8];
    const float* ln2_b  = (const float*)d_in[9];
    const float* ff1_w  = (const float*)d_in[10];
    const float* ff1_b  = (const float*)d_in[11];
    const float* ff2_w  = (const float*)d_in[12];
    const float* ff2_b  = (const float*)d_in[13];
    const float* lm_w   = (const float*)d_in[14];

    float* out = (float*)d_out;
    bool has_loss = ((long long)out_size == (long long)Mdim * Vdim + 1);
    float* logits = has_loss ? out + 1 : out;

    cudaFuncSetAttribute(gemm_tc_k, cudaFuncAttributeMaxDynamicSharedMemorySize, GT_SMEM);

    float *ph, *pqkv;
    cudaGetSymbolAddress((void**)&ph,   g_h);
    cudaGetSymbolAddress((void**)&pqkv, g_qkv);
    __nv_bfloat16 *wqh,*wql,*wf1h,*wf1l,*wf2h,*wf2l,*wlh,*wll;
    __nv_bfloat16 *xnh,*xnl,*fhh,*fhl,*ahh,*ahl;
    cudaGetSymbolAddress((void**)&wqh,  g_wqkv_hi);  cudaGetSymbolAddress((void**)&wql,  g_wqkv_lo);
    cudaGetSymbolAddress((void**)&wf1h, g_wff1_hi);  cudaGetSymbolAddress((void**)&wf1l, g_wff1_lo);
    cudaGetSymbolAddress((void**)&wf2h, g_wff2_hi);  cudaGetSymbolAddress((void**)&wf2l, g_wff2_lo);
    cudaGetSymbolAddress((void**)&wlh,  g_wlm_hi);   cudaGetSymbolAddress((void**)&wll,  g_wlm_lo);
    cudaGetSymbolAddress((void**)&xnh,  g_xn_hi);    cudaGetSymbolAddress((void**)&xnl,  g_xn_lo);
    cudaGetSymbolAddress((void**)&fhh,  g_ffh_hi);   cudaGetSymbolAddress((void**)&fhl,  g_ffh_lo);
    cudaGetSymbolAddress((void**)&ahh,  g_ah_hi);    cudaGetSymbolAddress((void**)&ahl,  g_ah_lo);

    // weight splits (hi/lo bf16)
    cvt_k<<<4096, 256>>>(attn_w, wqh,  wql,  (long)Ldim*C3*Cdim);
    cvt_k<<<4096, 256>>>(ff1_w,  wf1h, wf1l, (long)Ldim*Fdim*Cdim);
    cvt_k<<<4096, 256>>>(ff2_w,  wf2h, wf2l, (long)Ldim*Cdim*Fdim);
    cvt_k<<<8192, 256>>>(lm_w,   wlh,  wll,  (long)Vdim*Cdim);

    embed_k<<<(Mdim*Cdim + 255)/256, 256>>>(x, wte, wpe);

    for (int l = 0; l < Ldim; l++){
        ln_k<<<Mdim, 256>>>(ph, ln1_w + (size_t)l*Cdim, ln1_b + (size_t)l*Cdim, xnh, xnl);

        gemm_tc_k<<<dim3(Mdim/128, C3/128), 256, GT_SMEM>>>(
            xnh, xnl, wqh + (size_t)l*C3*Cdim, wql + (size_t)l*C3*Cdim,
            attn_b + (size_t)l*C3, pqkv, nullptr, nullptr, C3, Cdim, 0);

        attn_scores_k<<<dim3(Tdim/64, Tdim/64, Bdim*Hdim), 256>>>();
        softmax_k<<<Bdim*Hdim*Tdim, 256>>>();
        attn_av_k<<<dim3(Tdim/64, Bdim*Hdim), 256>>>();

        ln_k<<<Mdim, 256>>>(ph, ln2_w + (size_t)l*Cdim, ln2_b + (size_t)l*Cdim, xnh, xnl);

        gemm_tc_k<<<dim3(Mdim/128, Fdim/128), 256, GT_SMEM>>>(
            xnh, xnl, wf1h + (size_t)l*Fdim*Cdim, wf1l + (size_t)l*Fdim*Cdim,
            ff1_b + (size_t)l*Fdim, nullptr, fhh, fhl, Fdim, Cdim, 1);

        gemm_tc_k<<<dim3(Mdim/128, Cdim/128), 256, GT_SMEM>>>(
            fhh, fhl, wf2h + (size_t)l*Cdim*Fdim, wf2l + (size_t)l*Cdim*Fdim,
            ff2_b + (size_t)l*Cdim, ph, nullptr, nullptr, Cdim, Fdim, 2);
    }

    cvt_k<<<4096, 256>>>(ph, ahh, ahl, (long)Mdim*Cdim);

    gemm_tc_k<<<dim3(Mdim/128, (Vdim + 127)/128), 256, GT_SMEM>>>(
        ahh, ahl, wlh, wll, nullptr, logits, nullptr, nullptr, Vdim, Cdim, 3);

    loss_row_k<<<Mdim, 256>>>(logits, target);
    if (has_loss)
        loss_reduce_k<<<1, 256>>>(out);
}

// round 4
// speedup vs baseline: 2.3586x; 1.2673x over previous
#include <cuda_runtime.h>
#include <cuda_bf16.h>
#include <cstdint>
#include <math.h>

#define Bdim 2
#define Tdim 2048
#define Cdim 768
#define Hdim 12
#define Ddim 64
#define Ldim 6
#define Vdim 50257
#define Mdim (Bdim*Tdim)      /* 4096 */
#define C3   (3*Cdim)         /* 2304 */
#define Fdim (4*Cdim)         /* 3072 */

// ===================== device scratch (no allocations) ======================
__device__ float g_h  [Mdim*Cdim];
__device__ float g_rowloss[Mdim];

__device__ __nv_bfloat16 g_wqkv_hi[Ldim*C3*Cdim],  g_wqkv_lo[Ldim*C3*Cdim];
__device__ __nv_bfloat16 g_wff1_hi[Ldim*Fdim*Cdim], g_wff1_lo[Ldim*Fdim*Cdim];
__device__ __nv_bfloat16 g_wff2_hi[Ldim*Cdim*Fdim], g_wff2_lo[Ldim*Cdim*Fdim];
__device__ __nv_bfloat16 g_wlm_hi[(size_t)Vdim*Cdim], g_wlm_lo[(size_t)Vdim*Cdim];
__device__ __nv_bfloat16 g_xn_hi[Mdim*Cdim],  g_xn_lo[Mdim*Cdim];
__device__ __nv_bfloat16 g_ffh_hi[Mdim*Fdim], g_ffh_lo[Mdim*Fdim];
__device__ __nv_bfloat16 g_ah_hi[Mdim*Cdim],  g_ah_lo[Mdim*Cdim];
__device__ __nv_bfloat16 g_qkv_hi[Mdim*C3],   g_qkv_lo[Mdim*C3];

// ===================== asm helpers (baseline sm_80+ ISA) ====================
__device__ __forceinline__ uint32_t smem_to_u32(const void* p) {
    uint32_t a;
    asm("{ .reg .u64 t; cvta.to.shared.u64 t, %1; cvt.u32.u64 %0, t; }" : "=r"(a) : "l"(p));
    return a;
}
__device__ __forceinline__ void cp_async16(uint32_t dst, const void* src){
    asm volatile("cp.async.cg.shared.global [%0], [%1], 16;" :: "r"(dst), "l"(src));
}
#define CP_COMMIT() asm volatile("cp.async.commit_group;" ::: "memory")
#define CP_WAIT1()  asm volatile("cp.async.wait_group 1;" ::: "memory")
#define CP_WAIT0()  asm volatile("cp.async.wait_group 0;" ::: "memory")

__device__ __forceinline__ void ldsm_x4(uint32_t* r, uint32_t addr){
    asm volatile("ldmatrix.sync.aligned.m8n8.x4.shared.b16 {%0,%1,%2,%3}, [%4];"
        : "=r"(r[0]), "=r"(r[1]), "=r"(r[2]), "=r"(r[3]) : "r"(addr));
}
__device__ __forceinline__ void ldsm_x4_t(uint32_t* r, uint32_t addr){
    asm volatile("ldmatrix.sync.aligned.m8n8.x4.trans.shared.b16 {%0,%1,%2,%3}, [%4];"
        : "=r"(r[0]), "=r"(r[1]), "=r"(r[2]), "=r"(r[3]) : "r"(addr));
}
__device__ __forceinline__ void mma_bf16(float* d, const uint32_t* a,
                                         uint32_t b0, uint32_t b1){
    asm volatile("mma.sync.aligned.m16n8k16.row.col.f32.bf16.bf16.f32 "
        "{%0,%1,%2,%3}, {%4,%5,%6,%7}, {%8,%9}, {%0,%1,%2,%3};"
        : "+f"(d[0]), "+f"(d[1]), "+f"(d[2]), "+f"(d[3])
        : "r"(a[0]), "r"(a[1]), "r"(a[2]), "r"(a[3]), "r"(b0), "r"(b1));
}
__device__ __forceinline__ uint32_t pack_bf16x2(float lo, float hi){
    uint32_t r;
    asm("cvt.rn.bf16x2.f32 %0, %1, %2;" : "=r"(r) : "f"(hi), "f"(lo));
    return r;
}

// ===================== reductions ===========================================
__device__ __forceinline__ float blockReduceMax(float v){
    __shared__ float sh[8];
    int lid = threadIdx.x & 31, wid = threadIdx.x >> 5;
    #pragma unroll
    for (int o = 16; o > 0; o >>= 1) v = fmaxf(v, __shfl_xor_sync(0xffffffffu, v, o));
    if (lid == 0) sh[wid] = v;
    __syncthreads();
    v = sh[lid & 7];
    #pragma unroll
    for (int o = 4; o > 0; o >>= 1) v = fmaxf(v, __shfl_xor_sync(0xffffffffu, v, o));
    __syncthreads();
    return v;
}
__device__ __forceinline__ float blockReduceSum(float v){
    __shared__ float sh[8];
    int lid = threadIdx.x & 31, wid = threadIdx.x >> 5;
    #pragma unroll
    for (int o = 16; o > 0; o >>= 1) v += __shfl_xor_sync(0xffffffffu, v, o);
    if (lid == 0) sh[wid] = v;
    __syncthreads();
    v = sh[lid & 7];
    #pragma unroll
    for (int o = 4; o > 0; o >>= 1) v += __shfl_xor_sync(0xffffffffu, v, o);
    __syncthreads();
    return v;
}

// ===================== small kernels ========================================
__global__ void embed_k(const int* __restrict__ x,
                        const float* __restrict__ wte,
                        const float* __restrict__ wpe){
    int i = blockIdx.x * blockDim.x + threadIdx.x;
    if (i >= Mdim * Cdim) return;
    int c  = i % Cdim;
    int bt = i / Cdim;
    int t  = bt % Tdim;
    g_h[i] = wte[(size_t)x[bt] * Cdim + c] + wpe[(size_t)t * Cdim + c];
}

__global__ void cvt_k(const float* __restrict__ in, __nv_bfloat16* __restrict__ hi,
                      __nv_bfloat16* __restrict__ lo, long n){
    long stride = (long)gridDim.x * blockDim.x;
    for (long i = blockIdx.x * (long)blockDim.x + threadIdx.x; i < n; i += stride){
        float v = in[i];
        __nv_bfloat16 h = __float2bfloat16(v);
        hi[i] = h;
        lo[i] = __float2bfloat16(v - __bfloat162float(h));
    }
}

__global__ void ln_k(const float* __restrict__ in,
                     const float* __restrict__ w,
                     const float* __restrict__ b,
                     __nv_bfloat16* __restrict__ ohi,
                     __nv_bfloat16* __restrict__ olo){
    int row = blockIdx.x, tid = threadIdx.x;
    const float* xp = in + (size_t)row * Cdim;
    float v[3], s = 0.f, ss = 0.f;
    #pragma unroll
    for (int i = 0; i < 3; i++){
        v[i] = xp[tid + i * 256];
        s += v[i]; ss += v[i] * v[i];
    }
    s  = blockReduceSum(s);
    ss = blockReduceSum(ss);
    float mean = s * (1.f / Cdim);
    float var  = ss * (1.f / Cdim) - mean * mean;
    float rstd = rsqrtf(var + 1e-5f);
    #pragma unroll
    for (int i = 0; i < 3; i++){
        int c = tid + i * 256;
        float y = (v[i] - mean) * rstd * w[c] + b[c];
        __nv_bfloat16 h = __float2bfloat16(y);
        ohi[(size_t)row * Cdim + c] = h;
        olo[(size_t)row * Cdim + c] = __float2bfloat16(y - __bfloat162float(h));
    }
}

// ===================== tensor-core split-bf16 GEMM (mma.sync) ===============
// modes: 0: out_f = acc+bias | 1: relu(acc+bias)->hi/lo | 2: out_f += acc+bias
//        3: out_f = acc      | 4: (acc+bias)->hi/lo
#define MAT_B   10240            /* 128 rows * 80 bytes */
#define STG_B   (4*MAT_B)
#define GT_SMEM (2*STG_B)        /* 81920 bytes */

__global__ __launch_bounds__(256) void gemm_tc_k(
        const __nv_bfloat16* __restrict__ Ahi, const __nv_bfloat16* __restrict__ Alo,
        const __nv_bfloat16* __restrict__ Bhi, const __nv_bfloat16* __restrict__ Blo,
        const float* __restrict__ bias,
        float* __restrict__ out_f,
        __nv_bfloat16* __restrict__ out_hi, __nv_bfloat16* __restrict__ out_lo,
        int N, int K, int mode){
    extern __shared__ char smem[];
    uint32_t sbase = smem_to_u32(smem);
    int tid = threadIdx.x, wid = tid >> 5, lane = tid & 31;
    int warpRow = wid >> 2, warpCol = wid & 3;

    long row0 = (long)blockIdx.x * 128;
    long n0   = (long)blockIdx.y * 128;
    int nIter = K >> 5;

    float acc[4][4][4];
    #pragma unroll
    for (int i = 0; i < 4; i++)
        #pragma unroll
        for (int j = 0; j < 4; j++)
            #pragma unroll
            for (int q = 0; q < 4; q++) acc[i][j][q] = 0.f;

    auto issue = [&](int it){
        if (it >= nIter) return;
        int k0 = it << 5;
        uint32_t stg = sbase + (uint32_t)(it & 1) * STG_B;
        #pragma unroll
        for (int j = 0; j < 8; j++){
            int c   = tid + j * 256;
            int mat = c >> 9;
            int id  = c & 511;
            int row = id >> 2;
            int c8  = (id & 3) << 3;
            const __nv_bfloat16* src;
            if (mat < 2){
                src = (mat == 0 ? Ahi : Alo) + (row0 + row) * (long)K + k0 + c8;
            } else {
                long br = n0 + row; if (br >= N) br = 0;
                src = (mat == 2 ? Bhi : Blo) + br * (long)K + k0 + c8;
            }
            uint32_t dst = stg + (uint32_t)(mat * MAT_B + row * 80 + c8 * 2);
            cp_async16(dst, src);
        }
        CP_COMMIT();
    };

    issue(0);
    for (int it = 0; it < nIter; it++){
        issue(it + 1);
        if (it + 1 < nIter) CP_WAIT1(); else CP_WAIT0();
        __syncthreads();

        uint32_t stg = sbase + (uint32_t)(it & 1) * STG_B;
        uint32_t aHi = stg;
        uint32_t aLo = stg + MAT_B;
        uint32_t bHi = stg + 2*MAT_B;
        uint32_t bLo = stg + 3*MAT_B;
        uint32_t rsel = (uint32_t)(lane & 15) * 80 + (uint32_t)(lane >> 4) * 16;

        #pragma unroll
        for (int ks = 0; ks < 32; ks += 16){
            uint32_t ah[4][4], al[4][4];
            #pragma unroll
            for (int mi = 0; mi < 4; mi++){
                uint32_t off = (uint32_t)((warpRow*64 + mi*16) * 80 + ks*2) + rsel;
                ldsm_x4(ah[mi], aHi + off);
                ldsm_x4(al[mi], aLo + off);
            }
            uint32_t bh[2][4], bl[2][4];
            #pragma unroll
            for (int nj = 0; nj < 2; nj++){
                uint32_t off = (uint32_t)((warpCol*32 + nj*16) * 80 + ks*2) + rsel;
                ldsm_x4(bh[nj], bHi + off);
                ldsm_x4(bl[nj], bLo + off);
            }
            #pragma unroll
            for (int mi = 0; mi < 4; mi++)
                #pragma unroll
                for (int ni = 0; ni < 4; ni++){
                    int nj = ni >> 1, w = ni & 1;
                    mma_bf16(acc[mi][ni], ah[mi], bh[nj][w], bh[nj][w+2]);
                    mma_bf16(acc[mi][ni], ah[mi], bl[nj][w], bl[nj][w+2]);
                    mma_bf16(acc[mi][ni], al[mi], bh[nj][w], bh[nj][w+2]);
                }
        }
        __syncthreads();
    }

    #pragma unroll
    for (int mi = 0; mi < 4; mi++){
        long r0 = row0 + warpRow*64 + mi*16 + (lane >> 2);
        #pragma unroll
        for (int ni = 0; ni < 4; ni++){
            long c0 = n0 + warpCol*32 + ni*8 + (lane & 3)*2;
            #pragma unroll
            for (int half = 0; half < 2; half++){
                long r = r0 + half*8;
                #pragma unroll
                for (int e = 0; e < 2; e++){
                    long n = c0 + e;
                    if (n >= N) continue;
                    float v = acc[mi][ni][half*2 + e];
                    long oi = r * (long)N + n;
                    if (mode == 0){
                        out_f[oi] = v + bias[n];
                    } else if (mode == 1){
                        float y = fmaxf(v + bias[n], 0.f);
                        __nv_bfloat16 h = __float2bfloat16(y);
                        out_hi[oi] = h;
                        out_lo[oi] = __float2bfloat16(y - __bfloat162float(h));
                    } else if (mode == 2){
                        out_f[oi] += v + bias[n];
                    } else if (mode == 3){
                        out_f[oi] = v;
                    } else {
                        float y = v + bias[n];
                        __nv_bfloat16 h = __float2bfloat16(y);
                        out_hi[oi] = h;
                        out_lo[oi] = __float2bfloat16(y - __bfloat162float(h));
                    }
                }
            }
        }
    }
}

// ===================== flash attention (bf16 mma, hi/lo split) ==============
// CTA: one (b,h), 128 q rows; 8 warps x 16 rows. KV blocks of 64, double buf.
#define FA_QB    (128*144)           /* Q matrix bytes (stride 144B) */
#define FA_KVMAT (64*144)
#define FA_STGB  (4*FA_KVMAT)
#define FA_SMEM  (2*FA_QB + 2*FA_STGB)   /* 110592 */

__global__ __launch_bounds__(256) void flash_k(
        const __nv_bfloat16* __restrict__ qkvh,
        const __nv_bfloat16* __restrict__ qkvl){
    extern __shared__ char smem[];
    uint32_t sb = smem_to_u32(smem);
    uint32_t Qh = sb, Ql = sb + FA_QB;
    uint32_t kvb = sb + 2*FA_QB;

    int tid = threadIdx.x, wid = tid >> 5, lane = tid & 31;
    int g = lane >> 2, tq = lane & 3;
    int qb = (int)gridDim.x - 1 - (int)blockIdx.x;      // heavy blocks first
    int bh = blockIdx.y; int bq = bh / Hdim, head = bh % Hdim;
    int q0 = qb * 128;
    long rowbase = (long)bq * Tdim;

    // Q load (part of first cp.async group)
    #pragma unroll
    for (int j = 0; j < 8; j++){
        int id = tid + j*256;
        int mat = id >> 10, rem = id & 1023;
        int row = rem >> 3, c8 = (rem & 7) << 3;
        const __nv_bfloat16* src = (mat ? qkvl : qkvh)
            + (rowbase + q0 + row)*(long)C3 + head*Ddim + c8;
        cp_async16((mat ? Ql : Qh) + (uint32_t)(row*144 + c8*2), src);
    }

    int nkv = 2*qb + 2;
    auto issue = [&](int j){
        if (j >= nkv) return;
        int s0 = j * 64;
        uint32_t stg = kvb + (uint32_t)(j & 1) * FA_STGB;
        #pragma unroll
        for (int jj = 0; jj < 8; jj++){
            int id = tid + jj*256;
            int mat = id >> 9, rem = id & 511;
            int row = rem >> 3, c8 = (rem & 7) << 3;
            const __nv_bfloat16* base = (mat & 1) ? qkvl : qkvh;
            int coff = (mat < 2) ? Cdim : 2*Cdim;
            const __nv_bfloat16* src = base
                + (rowbase + s0 + row)*(long)C3 + coff + head*Ddim + c8;
            cp_async16(stg + (uint32_t)(mat*FA_KVMAT + row*144 + c8*2), src);
        }
        CP_COMMIT();
    };

    float mrow[2] = {-1e30f, -1e30f};
    float lrow[2] = {0.f, 0.f};
    float oacc[8][4];
    #pragma unroll
    for (int i = 0; i < 8; i++)
        #pragma unroll
        for (int e = 0; e < 4; e++) oacc[i][e] = 0.f;

    int t0w = q0 + wid*16;
    uint32_t rsel16 = (uint32_t)(lane & 15)*144 + (uint32_t)(lane >> 4)*16;
    int vtsel = lane >> 3, vrt = lane & 7;
    uint32_t vrow_off = ((vtsel >> 1) ? 8u : 0u) + (uint32_t)vrt;
    uint32_t vcol_off = (vtsel & 1) ? 16u : 0u;

    issue(0);
    for (int j = 0; j < nkv; j++){
        issue(j + 1);
        if (j + 1 < nkv) CP_WAIT1(); else CP_WAIT0();
        __syncthreads();

        int s0 = j * 64;
        if (s0 <= t0w + 15){                        // warp has unmasked rows
            uint32_t stg = kvb + (uint32_t)(j & 1) * FA_STGB;
            uint32_t Kh = stg, Kl = stg + FA_KVMAT;
            uint32_t Vh = stg + 2*FA_KVMAT, Vl = stg + 3*FA_KVMAT;

            float S[8][4];
            #pragma unroll
            for (int i = 0; i < 8; i++)
                #pragma unroll
                for (int e = 0; e < 4; e++) S[i][e] = 0.f;

            #pragma unroll
            for (int dc = 0; dc < 4; dc++){
                uint32_t aoff = (uint32_t)(wid*16)*144 + (uint32_t)dc*32 + rsel16;
                uint32_t ah[4], al[4];
                ldsm_x4(ah, Qh + aoff);
                ldsm_x4(al, Ql + aoff);
                #pragma unroll
                for (int ng = 0; ng < 4; ng++){
                    uint32_t boff = (uint32_t)(ng*16)*144 + (uint32_t)dc*32 + rsel16;
                    uint32_t kh[4], kl[4];
                    ldsm_x4(kh, Kh + boff);
                    ldsm_x4(kl, Kl + boff);
                    #pragma unroll
                    for (int w = 0; w < 2; w++){
                        mma_bf16(S[ng*2+w], ah, kh[w], kh[w+2]);
                        mma_bf16(S[ng*2+w], ah, kl[w], kl[w+2]);
                        mma_bf16(S[ng*2+w], al, kh[w], kh[w+2]);
                    }
                }
            }

            bool needMask = (s0 + 63 > t0w);
            #pragma unroll
            for (int ns = 0; ns < 8; ns++)
                #pragma unroll
                for (int e = 0; e < 4; e++){
                    float v = S[ns][e] * 0.125f;
                    if (needMask){
                        int t = t0w + g + (e >> 1)*8;
                        int s = s0 + ns*8 + tq*2 + (e & 1);
                        if (s > t) v = -1e30f;
                    }
                    S[ns][e] = v;
                }

            #pragma unroll
            for (int r = 0; r < 2; r++){
                float mx = -1e30f;
                #pragma unroll
                for (int ns = 0; ns < 8; ns++)
                    mx = fmaxf(mx, fmaxf(S[ns][r*2], S[ns][r*2+1]));
                mx = fmaxf(mx, __shfl_xor_sync(0xffffffffu, mx, 1));
                mx = fmaxf(mx, __shfl_xor_sync(0xffffffffu, mx, 2));
                float mnew = fmaxf(mrow[r], mx);
                float corr = __expf(mrow[r] - mnew);
                mrow[r] = mnew;
                float lsum = 0.f;
                #pragma unroll
                for (int ns = 0; ns < 8; ns++){
                    float p0 = __expf(S[ns][r*2]   - mnew);
                    float p1 = __expf(S[ns][r*2+1] - mnew);
                    S[ns][r*2] = p0; S[ns][r*2+1] = p1;
                    lsum += p0 + p1;
                }
                lsum += __shfl_xor_sync(0xffffffffu, lsum, 1);
                lsum += __shfl_xor_sync(0xffffffffu, lsum, 2);
                lrow[r] = lrow[r]*corr + lsum;
                #pragma unroll
                for (int dt = 0; dt < 8; dt++){
                    oacc[dt][r*2]   *= corr;
                    oacc[dt][r*2+1] *= corr;
                }
            }

            // P @ V  (S fragments reused as A fragments)
            #pragma unroll
            for (int sc = 0; sc < 4; sc++){
                uint32_t ph[4], pl[4];
                #pragma unroll
                for (int half = 0; half < 2; half++){
                    int ns = sc*2 + half;
                    float v0 = S[ns][0], v1 = S[ns][1], v2 = S[ns][2], v3 = S[ns][3];
                    float h0 = __bfloat162float(__float2bfloat16(v0));
                    float h1 = __bfloat162float(__float2bfloat16(v1));
                    float h2 = __bfloat162float(__float2bfloat16(v2));
                    float h3 = __bfloat162float(__float2bfloat16(v3));
                    ph[half*2+0] = pack_bf16x2(v0, v1);
                    ph[half*2+1] = pack_bf16x2(v2, v3);
                    pl[half*2+0] = pack_bf16x2(v0 - h0, v1 - h1);
                    pl[half*2+1] = pack_bf16x2(v2 - h2, v3 - h3);
                }
                // reorder to A-frag: a0=(g,k0-7) a1=(g+8,k0-7) a2=(g,k8-15) a3=(g+8,k8-15)
                uint32_t pa_h[4] = {ph[0], ph[1], ph[2], ph[3]};
                uint32_t pa_l[4] = {pl[0], pl[1], pl[2], pl[3]};
                uint32_t vbase = (uint32_t)((sc*16 + vrow_off)*144) + vcol_off;
                #pragma unroll
                for (int dg = 0; dg < 4; dg++){
                    uint32_t vh_[4], vl_[4];
                    ldsm_x4_t(vh_, Vh + vbase + (uint32_t)dg*32);
                    ldsm_x4_t(vl_, Vl + vbase + (uint32_t)dg*32);
                    #pragma unroll
                    for (int w = 0; w < 2; w++){
                        int dt = dg*2 + w;
                        mma_bf16(oacc[dt], pa_h, vh_[w], vh_[w+2]);
                        mma_bf16(oacc[dt], pa_h, vl_[w], vl_[w+2]);
                        mma_bf16(oacc[dt], pa_l, vh_[w], vh_[w+2]);
                    }
                }
            }
        }
        __syncthreads();
    }

    // epilogue: h += P@V / l
    #pragma unroll
    for (int r = 0; r < 2; r++){
        float inv = 1.f / lrow[r];
        long t = (long)t0w + g + r*8;
        float* hp = g_h + (rowbase + t)*(long)Cdim + head*Ddim;
        #pragma unroll
        for (int dt = 0; dt < 8; dt++){
            int d = dt*8 + tq*2;
            hp[d]   += oacc[dt][r*2]   * inv;
            hp[d+1] += oacc[dt][r*2+1] * inv;
        }
    }
}

// ===================== cross-entropy (single-pass online) ===================
__global__ void loss_row_k(const float* __restrict__ logits,
                           const int* __restrict__ target){
    int row = blockIdx.x, tid = threadIdx.x;
    const float* p = logits + (size_t)row * Vdim;
    float m = -1e30f, s = 0.f;
    for (int i = tid; i < Vdim; i += 256){
        float x = p[i];
        if (x > m){
            s = s * __expf(m - x) + 1.f;
            m = x;
        } else {
            s += __expf(x - m);
        }
    }
    float mg = blockReduceMax(m);
    s *= __expf(m - mg);
    float tot = blockReduceSum(s);
    if (tid == 0){
        float lse = logf(tot) + mg;
        g_rowloss[row] = lse - p[target[row]];
    }
}
__global__ void loss_reduce_k(float* out){
    float s = 0.f;
    for (int i = threadIdx.x; i < Mdim; i += 256) s += g_rowloss[i];
    s = blockReduceSum(s);
    if (threadIdx.x == 0) out[0] = s / (float)Mdim;
}

// ===================== launch ===============================================
extern "C" void kernel_launch(void* const* d_in, const int* in_sizes, int n_in,
                              void* d_out, int out_size){
    const int*   x      = (const int*)  d_in[0];
    const int*   target = (const int*)  d_in[1];
    const float* wte    = (const float*)d_in[2];
    const float* wpe    = (const float*)d_in[3];
    const float* ln1_w  = (const float*)d_in[4];
    const float* ln1_b  = (const float*)d_in[5];
    const float* attn_w = (const float*)d_in[6];
    const float* attn_b = (const float*)d_in[7];
    const float* ln2_w  = (const float*)d_in[8];
    const float* ln2_b  = (const float*)d_in[9];
    const float* ff1_w  = (const float*)d_in[10];
    const float* ff1_b  = (const float*)d_in[11];
    const float* ff2_w  = (const float*)d_in[12];
    const float* ff2_b  = (const float*)d_in[13];
    const float* lm_w   = (const float*)d_in[14];

    float* out = (float*)d_out;
    bool has_loss = ((long long)out_size == (long long)Mdim * Vdim + 1);
    float* logits = has_loss ? out + 1 : out;

    cudaFuncSetAttribute(gemm_tc_k, cudaFuncAttributeMaxDynamicSharedMemorySize, GT_SMEM);
    cudaFuncSetAttribute(flash_k,   cudaFuncAttributeMaxDynamicSharedMemorySize, FA_SMEM);

    float* ph;
    cudaGetSymbolAddress((void**)&ph, g_h);
    __nv_bfloat16 *wqh,*wql,*wf1h,*wf1l,*wf2h,*wf2l,*wlh,*wll;
    __nv_bfloat16 *xnh,*xnl,*fhh,*fhl,*ahh,*ahl,*qvh,*qvl;
    cudaGetSymbolAddress((void**)&wqh,  g_wqkv_hi);  cudaGetSymbolAddress((void**)&wql,  g_wqkv_lo);
    cudaGetSymbolAddress((void**)&wf1h, g_wff1_hi);  cudaGetSymbolAddress((void**)&wf1l, g_wff1_lo);
    cudaGetSymbolAddress((void**)&wf2h, g_wff2_hi);  cudaGetSymbolAddress((void**)&wf2l, g_wff2_lo);
    cudaGetSymbolAddress((void**)&wlh,  g_wlm_hi);   cudaGetSymbolAddress((void**)&wll,  g_wlm_lo);
    cudaGetSymbolAddress((void**)&xnh,  g_xn_hi);    cudaGetSymbolAddress((void**)&xnl,  g_xn_lo);
    cudaGetSymbolAddress((void**)&fhh,  g_ffh_hi);   cudaGetSymbolAddress((void**)&fhl,  g_ffh_lo);
    cudaGetSymbolAddress((void**)&ahh,  g_ah_hi);    cudaGetSymbolAddress((void**)&ahl,  g_ah_lo);
    cudaGetSymbolAddress((void**)&qvh,  g_qkv_hi);   cudaGetSymbolAddress((void**)&qvl,  g_qkv_lo);

    cvt_k<<<4096, 256>>>(attn_w, wqh,  wql,  (long)Ldim*C3*Cdim);
    cvt_k<<<4096, 256>>>(ff1_w,  wf1h, wf1l, (long)Ldim*Fdim*Cdim);
    cvt_k<<<4096, 256>>>(ff2_w,  wf2h, wf2l, (long)Ldim*Cdim*Fdim);
    cvt_k<<<8192, 256>>>(lm_w,   wlh,  wll,  (long)Vdim*Cdim);

    embed_k<<<(Mdim*Cdim + 255)/256, 256>>>(x, wte, wpe);

    for (int l = 0; l < Ldim; l++){
        ln_k<<<Mdim, 256>>>(ph, ln1_w + (size_t)l*Cdim, ln1_b + (size_t)l*Cdim, xnh, xnl);

        gemm_tc_k<<<dim3(Mdim/128, C3/128), 256, GT_SMEM>>>(
            xnh, xnl, wqh + (size_t)l*C3*Cdim, wql + (size_t)l*C3*Cdim,
            attn_b + (size_t)l*C3, nullptr, qvh, qvl, C3, Cdim, 4);

        flash_k<<<dim3(Tdim/128, Bdim*Hdim), 256, FA_SMEM>>>(qvh, qvl);

        ln_k<<<Mdim, 256>>>(ph, ln2_w + (size_t)l*Cdim, ln2_b + (size_t)l*Cdim, xnh, xnl);

        gemm_tc_k<<<dim3(Mdim/128, Fdim/128), 256, GT_SMEM>>>(
            xnh, xnl, wf1h + (size_t)l*Fdim*Cdim, wf1l + (size_t)l*Fdim*Cdim,
            ff1_b + (size_t)l*Fdim, nullptr, fhh, fhl, Fdim, Cdim, 1);

        gemm_tc_k<<<dim3(Mdim/128, Cdim/128), 256, GT_SMEM>>>(
            fhh, fhl, wf2h + (size_t)l*Cdim*Fdim, wf2l + (size_t)l*Cdim*Fdim,
            ff2_b + (size_t)l*Cdim, ph, nullptr, nullptr, Cdim, Fdim, 2);
    }

    cvt_k<<<4096, 256>>>(ph, ahh, ahl, (long)Mdim*Cdim);

    gemm_tc_k<<<dim3(Mdim/128, (Vdim + 127)/128), 256, GT_SMEM>>>(
        ahh, ahl, wlh, wll, nullptr, logits, nullptr, nullptr, Vdim, Cdim, 3);

    loss_row_k<<<Mdim, 256>>>(logits, target);
    if (has_loss)
        loss_reduce_k<<<1, 256>>>(out);
}

// round 5
// speedup vs baseline: 2.8657x; 1.2150x over previous
#include <cuda_runtime.h>
#include <cuda_bf16.h>
#include <cuda_fp16.h>
#include <cstdint>
#include <math.h>

#define Bdim 2
#define Tdim 2048
#define Cdim 768
#define Hdim 12
#define Ddim 64
#define Ldim 6
#define Vdim 50257
#define Mdim (Bdim*Tdim)      /* 4096 */
#define C3   (3*Cdim)         /* 2304 */
#define Fdim (4*Cdim)         /* 3072 */

// ===================== device scratch (no allocations) ======================
__device__ float g_h  [Mdim*Cdim];
__device__ float g_rowloss[Mdim];

__device__ __nv_bfloat16 g_wqkv_hi[Ldim*C3*Cdim],  g_wqkv_lo[Ldim*C3*Cdim];
__device__ __nv_bfloat16 g_wff1_hi[Ldim*Fdim*Cdim], g_wff1_lo[Ldim*Fdim*Cdim];
__device__ __nv_bfloat16 g_wff2_hi[Ldim*Cdim*Fdim], g_wff2_lo[Ldim*Cdim*Fdim];
__device__ __half        g_wlm_h[(size_t)Vdim*Cdim];
__device__ __nv_bfloat16 g_xn_hi[Mdim*Cdim],  g_xn_lo[Mdim*Cdim];
__device__ __nv_bfloat16 g_ffh_hi[Mdim*Fdim], g_ffh_lo[Mdim*Fdim];
__device__ __half        g_ah_h[Mdim*Cdim];
__device__ __nv_bfloat16 g_qkv_hi[Mdim*C3],   g_qkv_lo[Mdim*C3];

// ===================== asm helpers (baseline sm_80+ ISA) ====================
__device__ __forceinline__ uint32_t smem_to_u32(const void* p) {
    uint32_t a;
    asm("{ .reg .u64 t; cvta.to.shared.u64 t, %1; cvt.u32.u64 %0, t; }" : "=r"(a) : "l"(p));
    return a;
}
__device__ __forceinline__ void cp_async16(uint32_t dst, const void* src){
    asm volatile("cp.async.cg.shared.global [%0], [%1], 16;" :: "r"(dst), "l"(src));
}
#define CP_COMMIT() asm volatile("cp.async.commit_group;" ::: "memory")
#define CP_WAIT1()  asm volatile("cp.async.wait_group 1;" ::: "memory")
#define CP_WAIT0()  asm volatile("cp.async.wait_group 0;" ::: "memory")

__device__ __forceinline__ void ldsm_x4(uint32_t* r, uint32_t addr){
    asm volatile("ldmatrix.sync.aligned.m8n8.x4.shared.b16 {%0,%1,%2,%3}, [%4];"
        : "=r"(r[0]), "=r"(r[1]), "=r"(r[2]), "=r"(r[3]) : "r"(addr));
}
__device__ __forceinline__ void ldsm_x4_t(uint32_t* r, uint32_t addr){
    asm volatile("ldmatrix.sync.aligned.m8n8.x4.trans.shared.b16 {%0,%1,%2,%3}, [%4];"
        : "=r"(r[0]), "=r"(r[1]), "=r"(r[2]), "=r"(r[3]) : "r"(addr));
}
__device__ __forceinline__ void mma_bf16(float* d, const uint32_t* a,
                                         uint32_t b0, uint32_t b1){
    asm volatile("mma.sync.aligned.m16n8k16.row.col.f32.bf16.bf16.f32 "
        "{%0,%1,%2,%3}, {%4,%5,%6,%7}, {%8,%9}, {%0,%1,%2,%3};"
        : "+f"(d[0]), "+f"(d[1]), "+f"(d[2]), "+f"(d[3])
        : "r"(a[0]), "r"(a[1]), "r"(a[2]), "r"(a[3]), "r"(b0), "r"(b1));
}
__device__ __forceinline__ void mma_f16(float* d, const uint32_t* a,
                                        uint32_t b0, uint32_t b1){
    asm volatile("mma.sync.aligned.m16n8k16.row.col.f32.f16.f16.f32 "
        "{%0,%1,%2,%3}, {%4,%5,%6,%7}, {%8,%9}, {%0,%1,%2,%3};"
        : "+f"(d[0]), "+f"(d[1]), "+f"(d[2]), "+f"(d[3])
        : "r"(a[0]), "r"(a[1]), "r"(a[2]), "r"(a[3]), "r"(b0), "r"(b1));
}
__device__ __forceinline__ uint32_t pack_bf16x2(float lo, float hi){
    uint32_t r;
    asm("cvt.rn.bf16x2.f32 %0, %1, %2;" : "=r"(r) : "f"(hi), "f"(lo));
    return r;
}

// ===================== reductions ===========================================
__device__ __forceinline__ float blockReduceMax(float v){
    __shared__ float sh[8];
    int lid = threadIdx.x & 31, wid = threadIdx.x >> 5;
    #pragma unroll
    for (int o = 16; o > 0; o >>= 1) v = fmaxf(v, __shfl_xor_sync(0xffffffffu, v, o));
    if (lid == 0) sh[wid] = v;
    __syncthreads();
    v = sh[lid & 7];
    #pragma unroll
    for (int o = 4; o > 0; o >>= 1) v = fmaxf(v, __shfl_xor_sync(0xffffffffu, v, o));
    __syncthreads();
    return v;
}
__device__ __forceinline__ float blockReduceSum(float v){
    __shared__ float sh[8];
    int lid = threadIdx.x & 31, wid = threadIdx.x >> 5;
    #pragma unroll
    for (int o = 16; o > 0; o >>= 1) v += __shfl_xor_sync(0xffffffffu, v, o);
    if (lid == 0) sh[wid] = v;
    __syncthreads();
    v = sh[lid & 7];
    #pragma unroll
    for (int o = 4; o > 0; o >>= 1) v += __shfl_xor_sync(0xffffffffu, v, o);
    __syncthreads();
    return v;
}

// ===================== small kernels ========================================
__global__ void embed_k(const int* __restrict__ x,
                        const float* __restrict__ wte,
                        const float* __restrict__ wpe){
    int i = blockIdx.x * blockDim.x + threadIdx.x;
    if (i >= Mdim * Cdim) return;
    int c  = i % Cdim;
    int bt = i / Cdim;
    int t  = bt % Tdim;
    g_h[i] = wte[(size_t)x[bt] * Cdim + c] + wpe[(size_t)t * Cdim + c];
}

__global__ void cvt_k(const float* __restrict__ in, __nv_bfloat16* __restrict__ hi,
                      __nv_bfloat16* __restrict__ lo, long n){
    long stride = (long)gridDim.x * blockDim.x;
    for (long i = blockIdx.x * (long)blockDim.x + threadIdx.x; i < n; i += stride){
        float v = in[i];
        __nv_bfloat16 h = __float2bfloat16(v);
        hi[i] = h;
        lo[i] = __float2bfloat16(v - __bfloat162float(h));
    }
}

__global__ void cvt_h_k(const float* __restrict__ in, __half* __restrict__ o, long n){
    long stride = (long)gridDim.x * blockDim.x;
    for (long i = blockIdx.x * (long)blockDim.x + threadIdx.x; i < n; i += stride)
        o[i] = __float2half(in[i]);
}

__global__ void ln_k(const float* __restrict__ in,
                     const float* __restrict__ w,
                     const float* __restrict__ b,
                     __nv_bfloat16* __restrict__ ohi,
                     __nv_bfloat16* __restrict__ olo){
    int row = blockIdx.x, tid = threadIdx.x;
    const float* xp = in + (size_t)row * Cdim;
    float v[3], s = 0.f, ss = 0.f;
    #pragma unroll
    for (int i = 0; i < 3; i++){
        v[i] = xp[tid + i * 256];
        s += v[i]; ss += v[i] * v[i];
    }
    s  = blockReduceSum(s);
    ss = blockReduceSum(ss);
    float mean = s * (1.f / Cdim);
    float var  = ss * (1.f / Cdim) - mean * mean;
    float rstd = rsqrtf(var + 1e-5f);
    #pragma unroll
    for (int i = 0; i < 3; i++){
        int c = tid + i * 256;
        float y = (v[i] - mean) * rstd * w[c] + b[c];
        __nv_bfloat16 h = __float2bfloat16(y);
        ohi[(size_t)row * Cdim + c] = h;
        olo[(size_t)row * Cdim + c] = __float2bfloat16(y - __bfloat162float(h));
    }
}

// ===================== tensor-core split-bf16 GEMM (mma.sync) ===============
// modes: 0: out_f = acc+bias | 1: relu(acc+bias)->hi/lo | 2: out_f += acc+bias
//        3: out_f = acc      | 4: (acc+bias)->hi/lo
#define MAT_B   10240            /* 128 rows * 80 bytes */
#define STG_B   (4*MAT_B)
#define GT_SMEM (2*STG_B)        /* 81920 bytes */

__global__ __launch_bounds__(256) void gemm_tc_k(
        const __nv_bfloat16* __restrict__ Ahi, const __nv_bfloat16* __restrict__ Alo,
        const __nv_bfloat16* __restrict__ Bhi, const __nv_bfloat16* __restrict__ Blo,
        const float* __restrict__ bias,
        float* __restrict__ out_f,
        __nv_bfloat16* __restrict__ out_hi, __nv_bfloat16* __restrict__ out_lo,
        int N, int K, int mode){
    extern __shared__ char smem[];
    uint32_t sbase = smem_to_u32(smem);
    int tid = threadIdx.x, wid = tid >> 5, lane = tid & 31;
    int warpRow = wid >> 2, warpCol = wid & 3;

    long row0 = (long)blockIdx.x * 128;
    long n0   = (long)blockIdx.y * 128;
    int nIter = K >> 5;

    float acc[4][4][4];
    #pragma unroll
    for (int i = 0; i < 4; i++)
        #pragma unroll
        for (int j = 0; j < 4; j++)
            #pragma unroll
            for (int q = 0; q < 4; q++) acc[i][j][q] = 0.f;

    auto issue = [&](int it){
        if (it >= nIter) return;
        int k0 = it << 5;
        uint32_t stg = sbase + (uint32_t)(it & 1) * STG_B;
        #pragma unroll
        for (int j = 0; j < 8; j++){
            int c   = tid + j * 256;
            int mat = c >> 9;
            int id  = c & 511;
            int row = id >> 2;
            int c8  = (id & 3) << 3;
            const __nv_bfloat16* src;
            if (mat < 2){
                src = (mat == 0 ? Ahi : Alo) + (row0 + row) * (long)K + k0 + c8;
            } else {
                long br = n0 + row; if (br >= N) br = 0;
                src = (mat == 2 ? Bhi : Blo) + br * (long)K + k0 + c8;
            }
            uint32_t dst = stg + (uint32_t)(mat * MAT_B + row * 80 + c8 * 2);
            cp_async16(dst, src);
        }
        CP_COMMIT();
    };

    issue(0);
    for (int it = 0; it < nIter; it++){
        issue(it + 1);
        if (it + 1 < nIter) CP_WAIT1(); else CP_WAIT0();
        __syncthreads();

        uint32_t stg = sbase + (uint32_t)(it & 1) * STG_B;
        uint32_t aHi = stg;
        uint32_t aLo = stg + MAT_B;
        uint32_t bHi = stg + 2*MAT_B;
        uint32_t bLo = stg + 3*MAT_B;
        uint32_t rsel = (uint32_t)(lane & 15) * 80 + (uint32_t)(lane >> 4) * 16;

        #pragma unroll
        for (int ks = 0; ks < 32; ks += 16){
            uint32_t ah[4][4], al[4][4];
            #pragma unroll
            for (int mi = 0; mi < 4; mi++){
                uint32_t off = (uint32_t)((warpRow*64 + mi*16) * 80 + ks*2) + rsel;
                ldsm_x4(ah[mi], aHi + off);
                ldsm_x4(al[mi], aLo + off);
            }
            uint32_t bh[2][4], bl[2][4];
            #pragma unroll
            for (int nj = 0; nj < 2; nj++){
                uint32_t off = (uint32_t)((warpCol*32 + nj*16) * 80 + ks*2) + rsel;
                ldsm_x4(bh[nj], bHi + off);
                ldsm_x4(bl[nj], bLo + off);
            }
            #pragma unroll
            for (int mi = 0; mi < 4; mi++)
                #pragma unroll
                for (int ni = 0; ni < 4; ni++){
                    int nj = ni >> 1, w = ni & 1;
                    mma_bf16(acc[mi][ni], ah[mi], bh[nj][w], bh[nj][w+2]);
                    mma_bf16(acc[mi][ni], ah[mi], bl[nj][w], bl[nj][w+2]);
                    mma_bf16(acc[mi][ni], al[mi], bh[nj][w], bh[nj][w+2]);
                }
        }
        __syncthreads();
    }

    #pragma unroll
    for (int mi = 0; mi < 4; mi++){
        long r0 = row0 + warpRow*64 + mi*16 + (lane >> 2);
        #pragma unroll
        for (int ni = 0; ni < 4; ni++){
            long c0 = n0 + warpCol*32 + ni*8 + (lane & 3)*2;
            #pragma unroll
            for (int half = 0; half < 2; half++){
                long r = r0 + half*8;
                #pragma unroll
                for (int e = 0; e < 2; e++){
                    long n = c0 + e;
                    if (n >= N) continue;
                    float v = acc[mi][ni][half*2 + e];
                    long oi = r * (long)N + n;
                    if (mode == 0){
                        out_f[oi] = v + bias[n];
                    } else if (mode == 1){
                        float y = fmaxf(v + bias[n], 0.f);
                        __nv_bfloat16 h = __float2bfloat16(y);
                        out_hi[oi] = h;
                        out_lo[oi] = __float2bfloat16(y - __bfloat162float(h));
                    } else if (mode == 2){
                        out_f[oi] += v + bias[n];
                    } else if (mode == 3){
                        out_f[oi] = v;
                    } else {
                        float y = v + bias[n];
                        __nv_bfloat16 h = __float2bfloat16(y);
                        out_hi[oi] = h;
                        out_lo[oi] = __float2bfloat16(y - __bfloat162float(h));
                    }
                }
            }
        }
    }
}

// ===================== fp16 single-term GEMM (lm_head) ======================
#define FH_MAT  10240            /* 128 rows * 80 bytes */
#define FH_STG  (2*FH_MAT)
#define FH_SMEM (2*FH_STG)       /* 40960 */

__global__ __launch_bounds__(256) void gemm_f16_k(
        const __half* __restrict__ A, const __half* __restrict__ Bm,
        float* __restrict__ out_f, int N, int K){
    extern __shared__ char smem[];
    uint32_t sbase = smem_to_u32(smem);
    int tid = threadIdx.x, wid = tid >> 5, lane = tid & 31;
    int warpRow = wid >> 2, warpCol = wid & 3;

    long row0 = (long)blockIdx.x * 128;
    long n0   = (long)blockIdx.y * 128;
    int nIter = K >> 5;

    float acc[4][4][4];
    #pragma unroll
    for (int i = 0; i < 4; i++)
        #pragma unroll
        for (int j = 0; j < 4; j++)
            #pragma unroll
            for (int q = 0; q < 4; q++) acc[i][j][q] = 0.f;

    auto issue = [&](int it){
        if (it >= nIter) return;
        int k0 = it << 5;
        uint32_t stg = sbase + (uint32_t)(it & 1) * FH_STG;
        #pragma unroll
        for (int j = 0; j < 4; j++){
            int c   = tid + j * 256;          // 0..1023
            int mat = c >> 9;                  // 0:A 1:B
            int id  = c & 511;
            int row = id >> 2;
            int c8  = (id & 3) << 3;
            const __half* src;
            if (mat == 0){
                src = A + (row0 + row) * (long)K + k0 + c8;
            } else {
                long br = n0 + row; if (br >= N) br = 0;
                src = Bm + br * (long)K + k0 + c8;
            }
            uint32_t dst = stg + (uint32_t)(mat * FH_MAT + row * 80 + c8 * 2);
            cp_async16(dst, src);
        }
        CP_COMMIT();
    };

    issue(0);
    for (int it = 0; it < nIter; it++){
        issue(it + 1);
        if (it + 1 < nIter) CP_WAIT1(); else CP_WAIT0();
        __syncthreads();

        uint32_t stg = sbase + (uint32_t)(it & 1) * FH_STG;
        uint32_t aS = stg;
        uint32_t bS = stg + FH_MAT;
        uint32_t rsel = (uint32_t)(lane & 15) * 80 + (uint32_t)(lane >> 4) * 16;

        #pragma unroll
        for (int ks = 0; ks < 32; ks += 16){
            uint32_t af[4][4];
            #pragma unroll
            for (int mi = 0; mi < 4; mi++){
                uint32_t off = (uint32_t)((warpRow*64 + mi*16) * 80 + ks*2) + rsel;
                ldsm_x4(af[mi], aS + off);
            }
            uint32_t bf[2][4];
            #pragma unroll
            for (int nj = 0; nj < 2; nj++){
                uint32_t off = (uint32_t)((warpCol*32 + nj*16) * 80 + ks*2) + rsel;
                ldsm_x4(bf[nj], bS + off);
            }
            #pragma unroll
            for (int mi = 0; mi < 4; mi++)
                #pragma unroll
                for (int ni = 0; ni < 4; ni++){
                    int nj = ni >> 1, w = ni & 1;
                    mma_f16(acc[mi][ni], af[mi], bf[nj][w], bf[nj][w+2]);
                }
        }
        __syncthreads();
    }

    #pragma unroll
    for (int mi = 0; mi < 4; mi++){
        long r0 = row0 + warpRow*64 + mi*16 + (lane >> 2);
        #pragma unroll
        for (int ni = 0; ni < 4; ni++){
            long c0 = n0 + warpCol*32 + ni*8 + (lane & 3)*2;
            #pragma unroll
            for (int half = 0; half < 2; half++){
                long r = r0 + half*8;
                #pragma unroll
                for (int e = 0; e < 2; e++){
                    long n = c0 + e;
                    if (n < N)
                        out_f[r * (long)N + n] = acc[mi][ni][half*2 + e];
                }
            }
        }
    }
}

// ===================== flash attention (bf16 mma, hi/lo split) ==============
#define FA_QB    (128*144)
#define FA_KVMAT (64*144)
#define FA_STGB  (4*FA_KVMAT)
#define FA_SMEM  (2*FA_QB + 2*FA_STGB)   /* 110592 */

__global__ __launch_bounds__(256) void flash_k(
        const __nv_bfloat16* __restrict__ qkvh,
        const __nv_bfloat16* __restrict__ qkvl){
    extern __shared__ char smem[];
    uint32_t sb = smem_to_u32(smem);
    uint32_t Qh = sb, Ql = sb + FA_QB;
    uint32_t kvb = sb + 2*FA_QB;

    int tid = threadIdx.x, wid = tid >> 5, lane = tid & 31;
    int g = lane >> 2, tq = lane & 3;
    int qb = (int)gridDim.x - 1 - (int)blockIdx.x;
    int bh = blockIdx.y; int bq = bh / Hdim, head = bh % Hdim;
    int q0 = qb * 128;
    long rowbase = (long)bq * Tdim;

    #pragma unroll
    for (int j = 0; j < 8; j++){
        int id = tid + j*256;
        int mat = id >> 10, rem = id & 1023;
        int row = rem >> 3, c8 = (rem & 7) << 3;
        const __nv_bfloat16* src = (mat ? qkvl : qkvh)
            + (rowbase + q0 + row)*(long)C3 + head*Ddim + c8;
        cp_async16((mat ? Ql : Qh) + (uint32_t)(row*144 + c8*2), src);
    }

    int nkv = 2*qb + 2;
    auto issue = [&](int j){
        if (j >= nkv) return;
        int s0 = j * 64;
        uint32_t stg = kvb + (uint32_t)(j & 1) * FA_STGB;
        #pragma unroll
        for (int jj = 0; jj < 8; jj++){
            int id = tid + jj*256;
            int mat = id >> 9, rem = id & 511;
            int row = rem >> 3, c8 = (rem & 7) << 3;
            const __nv_bfloat16* base = (mat & 1) ? qkvl : qkvh;
            int coff = (mat < 2) ? Cdim : 2*Cdim;
            const __nv_bfloat16* src = base
                + (rowbase + s0 + row)*(long)C3 + coff + head*Ddim + c8;
            cp_async16(stg + (uint32_t)(mat*FA_KVMAT + row*144 + c8*2), src);
        }
        CP_COMMIT();
    };

    float mrow[2] = {-1e30f, -1e30f};
    float lrow[2] = {0.f, 0.f};
    float oacc[8][4];
    #pragma unroll
    for (int i = 0; i < 8; i++)
        #pragma unroll
        for (int e = 0; e < 4; e++) oacc[i][e] = 0.f;

    int t0w = q0 + wid*16;
    uint32_t rsel16 = (uint32_t)(lane & 15)*144 + (uint32_t)(lane >> 4)*16;
    int vtsel = lane >> 3, vrt = lane & 7;
    uint32_t vrow_off = ((vtsel >> 1) ? 8u : 0u) + (uint32_t)vrt;
    uint32_t vcol_off = (vtsel & 1) ? 16u : 0u;

    issue(0);
    for (int j = 0; j < nkv; j++){
        issue(j + 1);
        if (j + 1 < nkv) CP_WAIT1(); else CP_WAIT0();
        __syncthreads();

        int s0 = j * 64;
        if (s0 <= t0w + 15){
            uint32_t stg = kvb + (uint32_t)(j & 1) * FA_STGB;
            uint32_t Kh = stg, Kl = stg + FA_KVMAT;
            uint32_t Vh = stg + 2*FA_KVMAT, Vl = stg + 3*FA_KVMAT;

            float S[8][4];
            #pragma unroll
            for (int i = 0; i < 8; i++)
                #pragma unroll
                for (int e = 0; e < 4; e++) S[i][e] = 0.f;

            #pragma unroll
            for (int dc = 0; dc < 4; dc++){
                uint32_t aoff = (uint32_t)(wid*16)*144 + (uint32_t)dc*32 + rsel16;
                uint32_t ah[4], al[4];
                ldsm_x4(ah, Qh + aoff);
                ldsm_x4(al, Ql + aoff);
                #pragma unroll
                for (int ng = 0; ng < 4; ng++){
                    uint32_t boff = (uint32_t)(ng*16)*144 + (uint32_t)dc*32 + rsel16;
                    uint32_t kh[4], kl[4];
                    ldsm_x4(kh, Kh + boff);
                    ldsm_x4(kl, Kl + boff);
                    #pragma unroll
                    for (int w = 0; w < 2; w++){
                        mma_bf16(S[ng*2+w], ah, kh[w], kh[w+2]);
                        mma_bf16(S[ng*2+w], ah, kl[w], kl[w+2]);
                        mma_bf16(S[ng*2+w], al, kh[w], kh[w+2]);
                    }
                }
            }

            bool needMask = (s0 + 63 > t0w);
            #pragma unroll
            for (int ns = 0; ns < 8; ns++)
                #pragma unroll
                for (int e = 0; e < 4; e++){
                    float v = S[ns][e] * 0.125f;
                    if (needMask){
                        int t = t0w + g + (e >> 1)*8;
                        int s = s0 + ns*8 + tq*2 + (e & 1);
                        if (s > t) v = -1e30f;
                    }
                    S[ns][e] = v;
                }

            #pragma unroll
            for (int r = 0; r < 2; r++){
                float mx = -1e30f;
                #pragma unroll
                for (int ns = 0; ns < 8; ns++)
                    mx = fmaxf(mx, fmaxf(S[ns][r*2], S[ns][r*2+1]));
                mx = fmaxf(mx, __shfl_xor_sync(0xffffffffu, mx, 1));
                mx = fmaxf(mx, __shfl_xor_sync(0xffffffffu, mx, 2));
                float mnew = fmaxf(mrow[r], mx);
                float corr = __expf(mrow[r] - mnew);
                mrow[r] = mnew;
                float lsum = 0.f;
                #pragma unroll
                for (int ns = 0; ns < 8; ns++){
                    float p0 = __expf(S[ns][r*2]   - mnew);
                    float p1 = __expf(S[ns][r*2+1] - mnew);
                    S[ns][r*2] = p0; S[ns][r*2+1] = p1;
                    lsum += p0 + p1;
                }
                lsum += __shfl_xor_sync(0xffffffffu, lsum, 1);
                lsum += __shfl_xor_sync(0xffffffffu, lsum, 2);
                lrow[r] = lrow[r]*corr + lsum;
                #pragma unroll
                for (int dt = 0; dt < 8; dt++){
                    oacc[dt][r*2]   *= corr;
                    oacc[dt][r*2+1] *= corr;
                }
            }

            #pragma unroll
            for (int sc = 0; sc < 4; sc++){
                uint32_t ph[4], pl[4];
                #pragma unroll
                for (int half = 0; half < 2; half++){
                    int ns = sc*2 + half;
                    float v0 = S[ns][0], v1 = S[ns][1], v2 = S[ns][2], v3 = S[ns][3];
                    float h0 = __bfloat162float(__float2bfloat16(v0));
                    float h1 = __bfloat162float(__float2bfloat16(v1));
                    float h2 = __bfloat162float(__float2bfloat16(v2));
                    float h3 = __bfloat162float(__float2bfloat16(v3));
                    ph[half*2+0] = pack_bf16x2(v0, v1);
                    ph[half*2+1] = pack_bf16x2(v2, v3);
                    pl[half*2+0] = pack_bf16x2(v0 - h0, v1 - h1);
                    pl[half*2+1] = pack_bf16x2(v2 - h2, v3 - h3);
                }
                uint32_t pa_h[4] = {ph[0], ph[1], ph[2], ph[3]};
                uint32_t pa_l[4] = {pl[0], pl[1], pl[2], pl[3]};
                uint32_t vbase = (uint32_t)((sc*16 + vrow_off)*144) + vcol_off;
                #pragma unroll
                for (int dg = 0; dg < 4; dg++){
                    uint32_t vh_[4], vl_[4];
                    ldsm_x4_t(vh_, Vh + vbase + (uint32_t)dg*32);
                    ldsm_x4_t(vl_, Vl + vbase + (uint32_t)dg*32);
                    #pragma unroll
                    for (int w = 0; w < 2; w++){
                        int dt = dg*2 + w;
                        mma_bf16(oacc[dt], pa_h, vh_[w], vh_[w+2]);
                        mma_bf16(oacc[dt], pa_h, vl_[w], vl_[w+2]);
                        mma_bf16(oacc[dt], pa_l, vh_[w], vh_[w+2]);
                    }
                }
            }
        }
        __syncthreads();
    }

    #pragma unroll
    for (int r = 0; r < 2; r++){
        float inv = 1.f / lrow[r];
        long t = (long)t0w + g + r*8;
        float* hp = g_h + (rowbase + t)*(long)Cdim + head*Ddim;
        #pragma unroll
        for (int dt = 0; dt < 8; dt++){
            int d = dt*8 + tq*2;
            hp[d]   += oacc[dt][r*2]   * inv;
            hp[d+1] += oacc[dt][r*2+1] * inv;
        }
    }
}

// ===================== cross-entropy (single-pass online) ===================
__global__ void loss_row_k(const float* __restrict__ logits,
                           const int* __restrict__ target){
    int row = blockIdx.x, tid = threadIdx.x;
    const float* p = logits + (size_t)row * Vdim;
    float m = -1e30f, s = 0.f;
    for (int i = tid; i < Vdim; i += 256){
        float x = p[i];
        if (x > m){
            s = s * __expf(m - x) + 1.f;
            m = x;
        } else {
            s += __expf(x - m);
        }
    }
    float mg = blockReduceMax(m);
    s *= __expf(m - mg);
    float tot = blockReduceSum(s);
    if (tid == 0){
        float lse = logf(tot) + mg;
        g_rowloss[row] = lse - p[target[row]];
    }
}
__global__ void loss_reduce_k(float* out){
    float s = 0.f;
    for (int i = threadIdx.x; i < Mdim; i += 256) s += g_rowloss[i];
    s = blockReduceSum(s);
    if (threadIdx.x == 0) out[0] = s / (float)Mdim;
}

// ===================== launch ===============================================
extern "C" void kernel_launch(void* const* d_in, const int* in_sizes, int n_in,
                              void* d_out, int out_size){
    const int*   x      = (const int*)  d_in[0];
    const int*   target = (const int*)  d_in[1];
    const float* wte    = (const float*)d_in[2];
    const float* wpe    = (const float*)d_in[3];
    const float* ln1_w  = (const float*)d_in[4];
    const float* ln1_b  = (const float*)d_in[5];
    const float* attn_w = (const float*)d_in[6];
    const float* attn_b = (const float*)d_in[7];
    const float* ln2_w  = (const float*)d_in[8];
    const float* ln2_b  = (const float*)d_in[9];
    const float* ff1_w  = (const float*)d_in[10];
    const float* ff1_b  = (const float*)d_in[11];
    const float* ff2_w  = (const float*)d_in[12];
    const float* ff2_b  = (const float*)d_in[13];
    const float* lm_w   = (const float*)d_in[14];

    float* out = (float*)d_out;
    bool has_loss = ((long long)out_size == (long long)Mdim * Vdim + 1);
    float* logits = has_loss ? out + 1 : out;

    cudaFuncSetAttribute(gemm_tc_k,  cudaFuncAttributeMaxDynamicSharedMemorySize, GT_SMEM);
    cudaFuncSetAttribute(gemm_f16_k, cudaFuncAttributeMaxDynamicSharedMemorySize, FH_SMEM);
    cudaFuncSetAttribute(flash_k,    cudaFuncAttributeMaxDynamicSharedMemorySize, FA_SMEM);

    float* ph;
    cudaGetSymbolAddress((void**)&ph, g_h);
    __nv_bfloat16 *wqh,*wql,*wf1h,*wf1l,*wf2h,*wf2l;
    __nv_bfloat16 *xnh,*xnl,*fhh,*fhl,*qvh,*qvl;
    __half *wlh_h, *ah_h;
    cudaGetSymbolAddress((void**)&wqh,  g_wqkv_hi);  cudaGetSymbolAddress((void**)&wql,  g_wqkv_lo);
    cudaGetSymbolAddress((void**)&wf1h, g_wff1_hi);  cudaGetSymbolAddress((void**)&wf1l, g_wff1_lo);
    cudaGetSymbolAddress((void**)&wf2h, g_wff2_hi);  cudaGetSymbolAddress((void**)&wf2l, g_wff2_lo);
    cudaGetSymbolAddress((void**)&wlh_h, g_wlm_h);
    cudaGetSymbolAddress((void**)&xnh,  g_xn_hi);    cudaGetSymbolAddress((void**)&xnl,  g_xn_lo);
    cudaGetSymbolAddress((void**)&fhh,  g_ffh_hi);   cudaGetSymbolAddress((void**)&fhl,  g_ffh_lo);
    cudaGetSymbolAddress((void**)&ah_h, g_ah_h);
    cudaGetSymbolAddress((void**)&qvh,  g_qkv_hi);   cudaGetSymbolAddress((void**)&qvl,  g_qkv_lo);

    cvt_k<<<4096, 256>>>(attn_w, wqh,  wql,  (long)Ldim*C3*Cdim);
    cvt_k<<<4096, 256>>>(ff1_w,  wf1h, wf1l, (long)Ldim*Fdim*Cdim);
    cvt_k<<<4096, 256>>>(ff2_w,  wf2h, wf2l, (long)Ldim*Cdim*Fdim);
    cvt_h_k<<<8192, 256>>>(lm_w, wlh_h, (long)Vdim*Cdim);

    embed_k<<<(Mdim*Cdim + 255)/256, 256>>>(x, wte, wpe);

    for (int l = 0; l < Ldim; l++){
        ln_k<<<Mdim, 256>>>(ph, ln1_w + (size_t)l*Cdim, ln1_b + (size_t)l*Cdim, xnh, xnl);

        gemm_tc_k<<<dim3(Mdim/128, C3/128), 256, GT_SMEM>>>(
            xnh, xnl, wqh + (size_t)l*C3*Cdim, wql + (size_t)l*C3*Cdim,
            attn_b + (size_t)l*C3, nullptr, qvh, qvl, C3, Cdim, 4);

        flash_k<<<dim3(Tdim/128, Bdim*Hdim), 256, FA_SMEM>>>(qvh, qvl);

        ln_k<<<Mdim, 256>>>(ph, ln2_w + (size_t)l*Cdim, ln2_b + (size_t)l*Cdim, xnh, xnl);

        gemm_tc_k<<<dim3(Mdim/128, Fdim/128), 256, GT_SMEM>>>(
            xnh, xnl, wf1h + (size_t)l*Fdim*Cdim, wf1l + (size_t)l*Fdim*Cdim,
            ff1_b + (size_t)l*Fdim, nullptr, fhh, fhl, Fdim, Cdim, 1);

        gemm_tc_k<<<dim3(Mdim/128, Cdim/128), 256, GT_SMEM>>>(
            fhh, fhl, wf2h + (size_t)l*Cdim*Fdim, wf2l + (size_t)l*Cdim*Fdim,
            ff2_b + (size_t)l*Cdim, ph, nullptr, nullptr, Cdim, Fdim, 2);
    }

    cvt_h_k<<<4096, 256>>>(ph, ah_h, (long)Mdim*Cdim);

    gemm_f16_k<<<dim3(Mdim/128, (Vdim + 127)/128), 256, FH_SMEM>>>(
        ah_h, wlh_h, logits, Vdim, Cdim);

    loss_row_k<<<Mdim, 256>>>(logits, target);
    if (has_loss)
        loss_reduce_k<<<1, 256>>>(out);
}

// round 6
// speedup vs baseline: 3.1409x; 1.0960x over previous
#include <cuda_runtime.h>
#include <cuda_bf16.h>
#include <cuda_fp16.h>
#include <cstdint>
#include <math.h>

#define Bdim 2
#define Tdim 2048
#define Cdim 768
#define Hdim 12
#define Ddim 64
#define Ldim 6
#define Vdim 50257
#define Mdim (Bdim*Tdim)      /* 4096 */
#define C3   (3*Cdim)         /* 2304 */
#define Fdim (4*Cdim)         /* 3072 */

// ===================== device scratch (no allocations) ======================
__device__ float g_h  [Mdim*Cdim];
__device__ float g_rowloss[Mdim];

__device__ __nv_bfloat16 g_wqkv_hi[Ldim*C3*Cdim],  g_wqkv_lo[Ldim*C3*Cdim];
__device__ __nv_bfloat16 g_wff1_hi[Ldim*Fdim*Cdim], g_wff1_lo[Ldim*Fdim*Cdim];
__device__ __nv_bfloat16 g_wff2_hi[Ldim*Cdim*Fdim], g_wff2_lo[Ldim*Cdim*Fdim];
__device__ __half        g_wlm_h[(size_t)Vdim*Cdim];
__device__ __nv_bfloat16 g_xn_hi[Mdim*Cdim],  g_xn_lo[Mdim*Cdim];
__device__ __nv_bfloat16 g_ffh_hi[Mdim*Fdim], g_ffh_lo[Mdim*Fdim];
__device__ __half        g_ah_h[Mdim*Cdim];
__device__ __nv_bfloat16 g_qkv_hi[Mdim*C3],   g_qkv_lo[Mdim*C3];

// ===================== asm helpers (baseline sm_80+ ISA) ====================
__device__ __forceinline__ uint32_t smem_to_u32(const void* p) {
    uint32_t a;
    asm("{ .reg .u64 t; cvta.to.shared.u64 t, %1; cvt.u32.u64 %0, t; }" : "=r"(a) : "l"(p));
    return a;
}
__device__ __forceinline__ void cp_async16(uint32_t dst, const void* src){
    asm volatile("cp.async.cg.shared.global [%0], [%1], 16;" :: "r"(dst), "l"(src));
}
#define CP_COMMIT() asm volatile("cp.async.commit_group;" ::: "memory")
#define CP_WAIT1()  asm volatile("cp.async.wait_group 1;" ::: "memory")
#define CP_WAIT0()  asm volatile("cp.async.wait_group 0;" ::: "memory")

__device__ __forceinline__ void ldsm_x4(uint32_t* r, uint32_t addr){
    asm volatile("ldmatrix.sync.aligned.m8n8.x4.shared.b16 {%0,%1,%2,%3}, [%4];"
        : "=r"(r[0]), "=r"(r[1]), "=r"(r[2]), "=r"(r[3]) : "r"(addr));
}
__device__ __forceinline__ void ldsm_x4_t(uint32_t* r, uint32_t addr){
    asm volatile("ldmatrix.sync.aligned.m8n8.x4.trans.shared.b16 {%0,%1,%2,%3}, [%4];"
        : "=r"(r[0]), "=r"(r[1]), "=r"(r[2]), "=r"(r[3]) : "r"(addr));
}
__device__ __forceinline__ void mma_bf16(float* d, const uint32_t* a,
                                         uint32_t b0, uint32_t b1){
    asm volatile("mma.sync.aligned.m16n8k16.row.col.f32.bf16.bf16.f32 "
        "{%0,%1,%2,%3}, {%4,%5,%6,%7}, {%8,%9}, {%0,%1,%2,%3};"
        : "+f"(d[0]), "+f"(d[1]), "+f"(d[2]), "+f"(d[3])
        : "r"(a[0]), "r"(a[1]), "r"(a[2]), "r"(a[3]), "r"(b0), "r"(b1));
}
__device__ __forceinline__ void mma_f16(float* d, const uint32_t* a,
                                        uint32_t b0, uint32_t b1){
    asm volatile("mma.sync.aligned.m16n8k16.row.col.f32.f16.f16.f32 "
        "{%0,%1,%2,%3}, {%4,%5,%6,%7}, {%8,%9}, {%0,%1,%2,%3};"
        : "+f"(d[0]), "+f"(d[1]), "+f"(d[2]), "+f"(d[3])
        : "r"(a[0]), "r"(a[1]), "r"(a[2]), "r"(a[3]), "r"(b0), "r"(b1));
}
__device__ __forceinline__ uint32_t pack_bf16x2(float lo, float hi){
    uint32_t r;
    asm("cvt.rn.bf16x2.f32 %0, %1, %2;" : "=r"(r) : "f"(hi), "f"(lo));
    return r;
}

// ===================== reductions ===========================================
__device__ __forceinline__ float blockReduceMax(float v){
    __shared__ float sh[8];
    int lid = threadIdx.x & 31, wid = threadIdx.x >> 5;
    #pragma unroll
    for (int o = 16; o > 0; o >>= 1) v = fmaxf(v, __shfl_xor_sync(0xffffffffu, v, o));
    if (lid == 0) sh[wid] = v;
    __syncthreads();
    v = sh[lid & 7];
    #pragma unroll
    for (int o = 4; o > 0; o >>= 1) v = fmaxf(v, __shfl_xor_sync(0xffffffffu, v, o));
    __syncthreads();
    return v;
}
__device__ __forceinline__ float blockReduceSum(float v){
    __shared__ float sh[8];
    int lid = threadIdx.x & 31, wid = threadIdx.x >> 5;
    #pragma unroll
    for (int o = 16; o > 0; o >>= 1) v += __shfl_xor_sync(0xffffffffu, v, o);
    if (lid == 0) sh[wid] = v;
    __syncthreads();
    v = sh[lid & 7];
    #pragma unroll
    for (int o = 4; o > 0; o >>= 1) v += __shfl_xor_sync(0xffffffffu, v, o);
    __syncthreads();
    return v;
}

// ===================== small kernels ========================================
__global__ void embed_k(const int* __restrict__ x,
                        const float* __restrict__ wte,
                        const float* __restrict__ wpe){
    int i = blockIdx.x * blockDim.x + threadIdx.x;
    if (i >= Mdim * Cdim) return;
    int c  = i % Cdim;
    int bt = i / Cdim;
    int t  = bt % Tdim;
    g_h[i] = wte[(size_t)x[bt] * Cdim + c] + wpe[(size_t)t * Cdim + c];
}

// n must be a multiple of 4
__global__ void cvt_k(const float* __restrict__ in, __nv_bfloat16* __restrict__ hi,
                      __nv_bfloat16* __restrict__ lo, long n){
    long stride = (long)gridDim.x * blockDim.x * 4;
    for (long i = ((long)blockIdx.x * blockDim.x + threadIdx.x) * 4; i < n; i += stride){
        float4 v = *(const float4*)(in + i);
        __nv_bfloat16 h0 = __float2bfloat16(v.x), h1 = __float2bfloat16(v.y);
        __nv_bfloat16 h2 = __float2bfloat16(v.z), h3 = __float2bfloat16(v.w);
        uint2 hw, lw;
        hw.x = (uint32_t)__bfloat16_as_ushort(h0) | ((uint32_t)__bfloat16_as_ushort(h1) << 16);
        hw.y = (uint32_t)__bfloat16_as_ushort(h2) | ((uint32_t)__bfloat16_as_ushort(h3) << 16);
        lw.x = pack_bf16x2(v.x - __bfloat162float(h0), v.y - __bfloat162float(h1));
        lw.y = pack_bf16x2(v.z - __bfloat162float(h2), v.w - __bfloat162float(h3));
        *(uint2*)(hi + i) = hw;
        *(uint2*)(lo + i) = lw;
    }
}

__global__ void cvt_h_k(const float* __restrict__ in, __half* __restrict__ o, long n){
    long stride = (long)gridDim.x * blockDim.x * 4;
    for (long i = ((long)blockIdx.x * blockDim.x + threadIdx.x) * 4; i < n; i += stride){
        float4 v = *(const float4*)(in + i);
        __half2 a = __floats2half2_rn(v.x, v.y);
        __half2 b = __floats2half2_rn(v.z, v.w);
        uint2 w;
        w.x = *(uint32_t*)&a;
        w.y = *(uint32_t*)&b;
        *(uint2*)(o + i) = w;
    }
}

__global__ void ln_k(const float* __restrict__ in,
                     const float* __restrict__ w,
                     const float* __restrict__ b,
                     __nv_bfloat16* __restrict__ ohi,
                     __nv_bfloat16* __restrict__ olo){
    int row = blockIdx.x, tid = threadIdx.x;
    const float* xp = in + (size_t)row * Cdim;
    float v[3], s = 0.f, ss = 0.f;
    #pragma unroll
    for (int i = 0; i < 3; i++){
        v[i] = xp[tid + i * 256];
        s += v[i]; ss += v[i] * v[i];
    }
    s  = blockReduceSum(s);
    ss = blockReduceSum(ss);
    float mean = s * (1.f / Cdim);
    float var  = ss * (1.f / Cdim) - mean * mean;
    float rstd = rsqrtf(var + 1e-5f);
    #pragma unroll
    for (int i = 0; i < 3; i++){
        int c = tid + i * 256;
        float y = (v[i] - mean) * rstd * w[c] + b[c];
        __nv_bfloat16 h = __float2bfloat16(y);
        ohi[(size_t)row * Cdim + c] = h;
        olo[(size_t)row * Cdim + c] = __float2bfloat16(y - __bfloat162float(h));
    }
}

// ===================== tensor-core split-bf16 GEMM (mma.sync) ===============
// N must be a multiple of 128 (exact grid).
// modes: 1: relu(acc+bias)->hi/lo | 2: out_f += acc+bias (float2) | 4: (acc+bias)->hi/lo
#define MAT_B   10240            /* 128 rows * 80 bytes */
#define STG_B   (4*MAT_B)
#define GT_SMEM (2*STG_B)        /* 81920 bytes */

__global__ __launch_bounds__(256, 2) void gemm_tc_k(
        const __nv_bfloat16* __restrict__ Ahi, const __nv_bfloat16* __restrict__ Alo,
        const __nv_bfloat16* __restrict__ Bhi, const __nv_bfloat16* __restrict__ Blo,
        const float* __restrict__ bias,
        float* __restrict__ out_f,
        __nv_bfloat16* __restrict__ out_hi, __nv_bfloat16* __restrict__ out_lo,
        int N, int K, int mode){
    extern __shared__ char smem[];
    uint32_t sbase = smem_to_u32(smem);
    int tid = threadIdx.x, wid = tid >> 5, lane = tid & 31;
    int warpRow = wid >> 2, warpCol = wid & 3;

    long row0 = (long)blockIdx.x * 128;
    long n0   = (long)blockIdx.y * 128;
    int nIter = K >> 5;

    float acc[4][4][4];
    #pragma unroll
    for (int i = 0; i < 4; i++)
        #pragma unroll
        for (int j = 0; j < 4; j++)
            #pragma unroll
            for (int q = 0; q < 4; q++) acc[i][j][q] = 0.f;

    auto issue = [&](int it){
        if (it >= nIter) return;
        int k0 = it << 5;
        uint32_t stg = sbase + (uint32_t)(it & 1) * STG_B;
        #pragma unroll
        for (int j = 0; j < 8; j++){
            int c   = tid + j * 256;
            int mat = c >> 9;
            int id  = c & 511;
            int row = id >> 2;
            int c8  = (id & 3) << 3;
            const __nv_bfloat16* src;
            if (mat < 2){
                src = (mat == 0 ? Ahi : Alo) + (row0 + row) * (long)K + k0 + c8;
            } else {
                src = (mat == 2 ? Bhi : Blo) + (n0 + row) * (long)K + k0 + c8;
            }
            uint32_t dst = stg + (uint32_t)(mat * MAT_B + row * 80 + c8 * 2);
            cp_async16(dst, src);
        }
        CP_COMMIT();
    };

    issue(0);
    for (int it = 0; it < nIter; it++){
        issue(it + 1);
        if (it + 1 < nIter) CP_WAIT1(); else CP_WAIT0();
        __syncthreads();

        uint32_t stg = sbase + (uint32_t)(it & 1) * STG_B;
        uint32_t aHi = stg;
        uint32_t aLo = stg + MAT_B;
        uint32_t bHi = stg + 2*MAT_B;
        uint32_t bLo = stg + 3*MAT_B;
        uint32_t rsel = (uint32_t)(lane & 15) * 80 + (uint32_t)(lane >> 4) * 16;

        #pragma unroll
        for (int ks = 0; ks < 32; ks += 16){
            uint32_t bh[2][4], bl[2][4];
            #pragma unroll
            for (int nj = 0; nj < 2; nj++){
                uint32_t off = (uint32_t)((warpCol*32 + nj*16) * 80 + ks*2) + rsel;
                ldsm_x4(bh[nj], bHi + off);
                ldsm_x4(bl[nj], bLo + off);
            }
            #pragma unroll
            for (int mi = 0; mi < 4; mi++){
                uint32_t ah[4], al[4];
                uint32_t off = (uint32_t)((warpRow*64 + mi*16) * 80 + ks*2) + rsel;
                ldsm_x4(ah, aHi + off);
                ldsm_x4(al, aLo + off);
                #pragma unroll
                for (int ni = 0; ni < 4; ni++){
                    int nj = ni >> 1, w = ni & 1;
                    mma_bf16(acc[mi][ni], ah, bh[nj][w], bh[nj][w+2]);
                    mma_bf16(acc[mi][ni], ah, bl[nj][w], bl[nj][w+2]);
                    mma_bf16(acc[mi][ni], al, bh[nj][w], bh[nj][w+2]);
                }
            }
        }
        __syncthreads();
    }

    #pragma unroll
    for (int mi = 0; mi < 4; mi++){
        long r0 = row0 + warpRow*64 + mi*16 + (lane >> 2);
        #pragma unroll
        for (int ni = 0; ni < 4; ni++){
            long c0 = n0 + warpCol*32 + ni*8 + (lane & 3)*2;
            float b0 = bias[c0], b1 = bias[c0 + 1];
            #pragma unroll
            for (int half = 0; half < 2; half++){
                long r  = r0 + half*8;
                long oi = r * (long)N + c0;
                float v0 = acc[mi][ni][half*2]     + b0;
                float v1 = acc[mi][ni][half*2 + 1] + b1;
                if (mode == 2){
                    float2* p = (float2*)(out_f + oi);
                    float2 t = *p;
                    t.x += v0; t.y += v1;
                    *p = t;
                } else {
                    if (mode == 1){
                        v0 = fmaxf(v0, 0.f);
                        v1 = fmaxf(v1, 0.f);
                    }
                    float h0 = __bfloat162float(__float2bfloat16(v0));
                    float h1 = __bfloat162float(__float2bfloat16(v1));
                    *(uint32_t*)(out_hi + oi) = pack_bf16x2(v0, v1);
                    *(uint32_t*)(out_lo + oi) = pack_bf16x2(v0 - h0, v1 - h1);
                }
            }
        }
    }
}

// ===================== fp16 single-term GEMM (lm_head) ======================
#define FH_MAT  10240            /* 128 rows * 80 bytes */
#define FH_STG  (2*FH_MAT)
#define FH_SMEM (2*FH_STG)       /* 40960 */

__global__ __launch_bounds__(256, 2) void gemm_f16_k(
        const __half* __restrict__ A, const __half* __restrict__ Bm,
        float* __restrict__ out_f, int N, int K){
    extern __shared__ char smem[];
    uint32_t sbase = smem_to_u32(smem);
    int tid = threadIdx.x, wid = tid >> 5, lane = tid & 31;
    int warpRow = wid >> 2, warpCol = wid & 3;

    long row0 = (long)blockIdx.x * 128;
    long n0   = (long)blockIdx.y * 128;
    int nIter = K >> 5;

    float acc[4][4][4];
    #pragma unroll
    for (int i = 0; i < 4; i++)
        #pragma unroll
        for (int j = 0; j < 4; j++)
            #pragma unroll
            for (int q = 0; q < 4; q++) acc[i][j][q] = 0.f;

    auto issue = [&](int it){
        if (it >= nIter) return;
        int k0 = it << 5;
        uint32_t stg = sbase + (uint32_t)(it & 1) * FH_STG;
        #pragma unroll
        for (int j = 0; j < 4; j++){
            int c   = tid + j * 256;
            int mat = c >> 9;
            int id  = c & 511;
            int row = id >> 2;
            int c8  = (id & 3) << 3;
            const __half* src;
            if (mat == 0){
                src = A + (row0 + row) * (long)K + k0 + c8;
            } else {
                long br = n0 + row; if (br >= N) br = 0;
                src = Bm + br * (long)K + k0 + c8;
            }
            uint32_t dst = stg + (uint32_t)(mat * FH_MAT + row * 80 + c8 * 2);
            cp_async16(dst, src);
        }
        CP_COMMIT();
    };

    issue(0);
    for (int it = 0; it < nIter; it++){
        issue(it + 1);
        if (it + 1 < nIter) CP_WAIT1(); else CP_WAIT0();
        __syncthreads();

        uint32_t stg = sbase + (uint32_t)(it & 1) * FH_STG;
        uint32_t aS = stg;
        uint32_t bS = stg + FH_MAT;
        uint32_t rsel = (uint32_t)(lane & 15) * 80 + (uint32_t)(lane >> 4) * 16;

        #pragma unroll
        for (int ks = 0; ks < 32; ks += 16){
            uint32_t bf[2][4];
            #pragma unroll
            for (int nj = 0; nj < 2; nj++){
                uint32_t off = (uint32_t)((warpCol*32 + nj*16) * 80 + ks*2) + rsel;
                ldsm_x4(bf[nj], bS + off);
            }
            #pragma unroll
            for (int mi = 0; mi < 4; mi++){
                uint32_t af[4];
                uint32_t off = (uint32_t)((warpRow*64 + mi*16) * 80 + ks*2) + rsel;
                ldsm_x4(af, aS + off);
                #pragma unroll
                for (int ni = 0; ni < 4; ni++){
                    int nj = ni >> 1, w = ni & 1;
                    mma_f16(acc[mi][ni], af, bf[nj][w], bf[nj][w+2]);
                }
            }
        }
        __syncthreads();
    }

    // scalar stores: logits base pointer may be only 4B-aligned (out+1)
    #pragma unroll
    for (int mi = 0; mi < 4; mi++){
        long r0 = row0 + warpRow*64 + mi*16 + (lane >> 2);
        #pragma unroll
        for (int ni = 0; ni < 4; ni++){
            long c0 = n0 + warpCol*32 + ni*8 + (lane & 3)*2;
            #pragma unroll
            for (int half = 0; half < 2; half++){
                long r = r0 + half*8;
                #pragma unroll
                for (int e = 0; e < 2; e++){
                    long n = c0 + e;
                    if (n < N)
                        out_f[r * (long)N + n] = acc[mi][ni][half*2 + e];
                }
            }
        }
    }
}

// ===================== flash attention (bf16 mma, hi/lo split) ==============
#define FA_QB    (128*144)
#define FA_KVMAT (64*144)
#define FA_STGB  (4*FA_KVMAT)
#define FA_SMEM  (2*FA_QB + 2*FA_STGB)   /* 110592 */

__global__ __launch_bounds__(256, 2) void flash_k(
        const __nv_bfloat16* __restrict__ qkvh,
        const __nv_bfloat16* __restrict__ qkvl){
    extern __shared__ char smem[];
    uint32_t sb = smem_to_u32(smem);
    uint32_t Qh = sb, Ql = sb + FA_QB;
    uint32_t kvb = sb + 2*FA_QB;

    int tid = threadIdx.x, wid = tid >> 5, lane = tid & 31;
    int g = lane >> 2, tq = lane & 3;
    int qb = (int)gridDim.x - 1 - (int)blockIdx.x;
    int bh = blockIdx.y; int bq = bh / Hdim, head = bh % Hdim;
    int q0 = qb * 128;
    long rowbase = (long)bq * Tdim;

    #pragma unroll
    for (int j = 0; j < 8; j++){
        int id = tid + j*256;
        int mat = id >> 10, rem = id & 1023;
        int row = rem >> 3, c8 = (rem & 7) << 3;
        const __nv_bfloat16* src = (mat ? qkvl : qkvh)
            + (rowbase + q0 + row)*(long)C3 + head*Ddim + c8;
        cp_async16((mat ? Ql : Qh) + (uint32_t)(row*144 + c8*2), src);
    }

    int nkv = 2*qb + 2;
    auto issue = [&](int j){
        if (j >= nkv) return;
        int s0 = j * 64;
        uint32_t stg = kvb + (uint32_t)(j & 1) * FA_STGB;
        #pragma unroll
        for (int jj = 0; jj < 8; jj++){
            int id = tid + jj*256;
            int mat = id >> 9, rem = id & 511;
            int row = rem >> 3, c8 = (rem & 7) << 3;
            const __nv_bfloat16* base = (mat & 1) ? qkvl : qkvh;
            int coff = (mat < 2) ? Cdim : 2*Cdim;
            const __nv_bfloat16* src = base
                + (rowbase + s0 + row)*(long)C3 + coff + head*Ddim + c8;
            cp_async16(stg + (uint32_t)(mat*FA_KVMAT + row*144 + c8*2), src);
        }
        CP_COMMIT();
    };

    float mrow[2] = {-1e30f, -1e30f};
    float lrow[2] = {0.f, 0.f};
    float oacc[8][4];
    #pragma unroll
    for (int i = 0; i < 8; i++)
        #pragma unroll
        for (int e = 0; e < 4; e++) oacc[i][e] = 0.f;

    int t0w = q0 + wid*16;
    uint32_t rsel16 = (uint32_t)(lane & 15)*144 + (uint32_t)(lane >> 4)*16;
    int vtsel = lane >> 3, vrt = lane & 7;
    uint32_t vrow_off = ((vtsel >> 1) ? 8u : 0u) + (uint32_t)vrt;
    uint32_t vcol_off = (vtsel & 1) ? 16u : 0u;

    issue(0);
    for (int j = 0; j < nkv; j++){
        issue(j + 1);
        if (j + 1 < nkv) CP_WAIT1(); else CP_WAIT0();
        __syncthreads();

        int s0 = j * 64;
        if (s0 <= t0w + 15){
            uint32_t stg = kvb + (uint32_t)(j & 1) * FA_STGB;
            uint32_t Kh = stg, Kl = stg + FA_KVMAT;
            uint32_t Vh = stg + 2*FA_KVMAT, Vl = stg + 3*FA_KVMAT;

            float S[8][4];
            #pragma unroll
            for (int i = 0; i < 8; i++)
                #pragma unroll
                for (int e = 0; e < 4; e++) S[i][e] = 0.f;

            #pragma unroll
            for (int dc = 0; dc < 4; dc++){
                uint32_t aoff = (uint32_t)(wid*16)*144 + (uint32_t)dc*32 + rsel16;
                uint32_t ah[4], al[4];
                ldsm_x4(ah, Qh + aoff);
                ldsm_x4(al, Ql + aoff);
                #pragma unroll
                for (int ng = 0; ng < 4; ng++){
                    uint32_t boff = (uint32_t)(ng*16)*144 + (uint32_t)dc*32 + rsel16;
                    uint32_t kh[4], kl[4];
                    ldsm_x4(kh, Kh + boff);
                    ldsm_x4(kl, Kl + boff);
                    #pragma unroll
                    for (int w = 0; w < 2; w++){
                        mma_bf16(S[ng*2+w], ah, kh[w], kh[w+2]);
                        mma_bf16(S[ng*2+w], ah, kl[w], kl[w+2]);
                        mma_bf16(S[ng*2+w], al, kh[w], kh[w+2]);
                    }
                }
            }

            bool needMask = (s0 + 63 > t0w);
            #pragma unroll
            for (int ns = 0; ns < 8; ns++)
                #pragma unroll
                for (int e = 0; e < 4; e++){
                    float v = S[ns][e] * 0.125f;
                    if (needMask){
                        int t = t0w + g + (e >> 1)*8;
                        int s = s0 + ns*8 + tq*2 + (e & 1);
                        if (s > t) v = -1e30f;
                    }
                    S[ns][e] = v;
                }

            #pragma unroll
            for (int r = 0; r < 2; r++){
                float mx = -1e30f;
                #pragma unroll
                for (int ns = 0; ns < 8; ns++)
                    mx = fmaxf(mx, fmaxf(S[ns][r*2], S[ns][r*2+1]));
                mx = fmaxf(mx, __shfl_xor_sync(0xffffffffu, mx, 1));
                mx = fmaxf(mx, __shfl_xor_sync(0xffffffffu, mx, 2));
                float mnew = fmaxf(mrow[r], mx);
                float corr = __expf(mrow[r] - mnew);
                mrow[r] = mnew;
                float lsum = 0.f;
                #pragma unroll
                for (int ns = 0; ns < 8; ns++){
                    float p0 = __expf(S[ns][r*2]   - mnew);
                    float p1 = __expf(S[ns][r*2+1] - mnew);
                    S[ns][r*2] = p0; S[ns][r*2+1] = p1;
                    lsum += p0 + p1;
                }
                lsum += __shfl_xor_sync(0xffffffffu, lsum, 1);
                lsum += __shfl_xor_sync(0xffffffffu, lsum, 2);
                lrow[r] = lrow[r]*corr + lsum;
                #pragma unroll
                for (int dt = 0; dt < 8; dt++){
                    oacc[dt][r*2]   *= corr;
                    oacc[dt][r*2+1] *= corr;
                }
            }

            #pragma unroll
            for (int sc = 0; sc < 4; sc++){
                uint32_t ph[4], pl[4];
                #pragma unroll
                for (int half = 0; half < 2; half++){
                    int ns = sc*2 + half;
                    float v0 = S[ns][0], v1 = S[ns][1], v2 = S[ns][2], v3 = S[ns][3];
                    float h0 = __bfloat162float(__float2bfloat16(v0));
                    float h1 = __bfloat162float(__float2bfloat16(v1));
                    float h2 = __bfloat162float(__float2bfloat16(v2));
                    float h3 = __bfloat162float(__float2bfloat16(v3));
                    ph[half*2+0] = pack_bf16x2(v0, v1);
                    ph[half*2+1] = pack_bf16x2(v2, v3);
                    pl[half*2+0] = pack_bf16x2(v0 - h0, v1 - h1);
                    pl[half*2+1] = pack_bf16x2(v2 - h2, v3 - h3);
                }
                uint32_t vbase = (uint32_t)((sc*16 + vrow_off)*144) + vcol_off;
                #pragma unroll
                for (int dg = 0; dg < 4; dg++){
                    uint32_t vh_[4], vl_[4];
                    ldsm_x4_t(vh_, Vh + vbase + (uint32_t)dg*32);
                    ldsm_x4_t(vl_, Vl + vbase + (uint32_t)dg*32);
                    #pragma unroll
                    for (int w = 0; w < 2; w++){
                        int dt = dg*2 + w;
                        mma_bf16(oacc[dt], ph, vh_[w], vh_[w+2]);
                        mma_bf16(oacc[dt], ph, vl_[w], vl_[w+2]);
                        mma_bf16(oacc[dt], pl, vh_[w], vh_[w+2]);
                    }
                }
            }
        }
        __syncthreads();
    }

    #pragma unroll
    for (int r = 0; r < 2; r++){
        float inv = 1.f / lrow[r];
        long t = (long)t0w + g + r*8;
        float* hp = g_h + (rowbase + t)*(long)Cdim + head*Ddim;
        #pragma unroll
        for (int dt = 0; dt < 8; dt++){
            float2* p = (float2*)(hp + dt*8 + tq*2);
            float2 v = *p;
            v.x += oacc[dt][r*2]   * inv;
            v.y += oacc[dt][r*2+1] * inv;
            *p = v;
        }
    }
}

// ===================== cross-entropy (single-pass online) ===================
__global__ void loss_row_k(const float* __restrict__ logits,
                           const int* __restrict__ target){
    int row = blockIdx.x, tid = threadIdx.x;
    const float* p = logits + (size_t)row * Vdim;
    float m = -1e30f, s = 0.f;
    for (int i = tid; i < Vdim; i += 256){
        float x = p[i];
        if (x > m){
            s = s * __expf(m - x) + 1.f;
            m = x;
        } else {
            s += __expf(x - m);
        }
    }
    float mg = blockReduceMax(m);
    s *= __expf(m - mg);
    float tot = blockReduceSum(s);
    if (tid == 0){
        float lse = logf(tot) + mg;
        g_rowloss[row] = lse - p[target[row]];
    }
}
__global__ void loss_reduce_k(float* out){
    float s = 0.f;
    for (int i = threadIdx.x; i < Mdim; i += 256) s += g_rowloss[i];
    s = blockReduceSum(s);
    if (threadIdx.x == 0) out[0] = s / (float)Mdim;
}

// ===================== launch ===============================================
extern "C" void kernel_launch(void* const* d_in, const int* in_sizes, int n_in,
                              void* d_out, int out_size){
    const int*   x      = (const int*)  d_in[0];
    const int*   target = (const int*)  d_in[1];
    const float* wte    = (const float*)d_in[2];
    const float* wpe    = (const float*)d_in[3];
    const float* ln1_w  = (const float*)d_in[4];
    const float* ln1_b  = (const float*)d_in[5];
    const float* attn_w = (const float*)d_in[6];
    const float* attn_b = (const float*)d_in[7];
    const float* ln2_w  = (const float*)d_in[8];
    const float* ln2_b  = (const float*)d_in[9];
    const float* ff1_w  = (const float*)d_in[10];
    const float* ff1_b  = (const float*)d_in[11];
    const float* ff2_w  = (const float*)d_in[12];
    const float* ff2_b  = (const float*)d_in[13];
    const float* lm_w   = (const float*)d_in[14];

    float* out = (float*)d_out;
    bool has_loss = ((long long)out_size == (long long)Mdim * Vdim + 1);
    float* logits = has_loss ? out + 1 : out;

    cudaFuncSetAttribute(gemm_tc_k,  cudaFuncAttributeMaxDynamicSharedMemorySize, GT_SMEM);
    cudaFuncSetAttribute(gemm_f16_k, cudaFuncAttributeMaxDynamicSharedMemorySize, FH_SMEM);
    cudaFuncSetAttribute(flash_k,    cudaFuncAttributeMaxDynamicSharedMemorySize, FA_SMEM);

    float* ph;
    cudaGetSymbolAddress((void**)&ph, g_h);
    __nv_bfloat16 *wqh,*wql,*wf1h,*wf1l,*wf2h,*wf2l;
    __nv_bfloat16 *xnh,*xnl,*fhh,*fhl,*qvh,*qvl;
    __half *wlh_h, *ah_h;
    cudaGetSymbolAddress((void**)&wqh,  g_wqkv_hi);  cudaGetSymbolAddress((void**)&wql,  g_wqkv_lo);
    cudaGetSymbolAddress((void**)&wf1h, g_wff1_hi);  cudaGetSymbolAddress((void**)&wf1l, g_wff1_lo);
    cudaGetSymbolAddress((void**)&wf2h, g_wff2_hi);  cudaGetSymbolAddress((void**)&wf2l, g_wff2_lo);
    cudaGetSymbolAddress((void**)&wlh_h, g_wlm_h);
    cudaGetSymbolAddress((void**)&xnh,  g_xn_hi);    cudaGetSymbolAddress((void**)&xnl,  g_xn_lo);
    cudaGetSymbolAddress((void**)&fhh,  g_ffh_hi);   cudaGetSymbolAddress((void**)&fhl,  g_ffh_lo);
    cudaGetSymbolAddress((void**)&ah_h, g_ah_h);
    cudaGetSymbolAddress((void**)&qvh,  g_qkv_hi);   cudaGetSymbolAddress((void**)&qvl,  g_qkv_lo);

    cvt_k<<<2048, 256>>>(attn_w, wqh,  wql,  (long)Ldim*C3*Cdim);
    cvt_k<<<2048, 256>>>(ff1_w,  wf1h, wf1l, (long)Ldim*Fdim*Cdim);
    cvt_k<<<2048, 256>>>(ff2_w,  wf2h, wf2l, (long)Ldim*Cdim*Fdim);
    cvt_h_k<<<4096, 256>>>(lm_w, wlh_h, (long)Vdim*Cdim);

    embed_k<<<(Mdim*Cdim + 255)/256, 256>>>(x, wte, wpe);

    for (int l = 0; l < Ldim; l++){
        ln_k<<<Mdim, 256>>>(ph, ln1_w + (size_t)l*Cdim, ln1_b + (size_t)l*Cdim, xnh, xnl);

        gemm_tc_k<<<dim3(Mdim/128, C3/128), 256, GT_SMEM>>>(
            xnh, xnl, wqh + (size_t)l*C3*Cdim, wql + (size_t)l*C3*Cdim,
            attn_b + (size_t)l*C3, nullptr, qvh, qvl, C3, Cdim, 4);

        flash_k<<<dim3(Tdim/128, Bdim*Hdim), 256, FA_SMEM>>>(qvh, qvl);

        ln_k<<<Mdim, 256>>>(ph, ln2_w + (size_t)l*Cdim, ln2_b + (size_t)l*Cdim, xnh, xnl);

        gemm_tc_k<<<dim3(Mdim/128, Fdim/128), 256, GT_SMEM>>>(
            xnh, xnl, wf1h + (size_t)l*Fdim*Cdim, wf1l + (size_t)l*Fdim*Cdim,
            ff1_b + (size_t)l*Fdim, nullptr, fhh, fhl, Fdim, Cdim, 1);

        gemm_tc_k<<<dim3(Mdim/128, Cdim/128), 256, GT_SMEM>>>(
            fhh, fhl, wf2h + (size_t)l*Cdim*Fdim, wf2l + (size_t)l*Cdim*Fdim,
            ff2_b + (size_t)l*Cdim, ph, nullptr, nullptr, Cdim, Fdim, 2);
    }

    cvt_h_k<<<2048, 256>>>(ph, ah_h, (long)Mdim*Cdim);

    gemm_f16_k<<<dim3(Mdim/128, (Vdim + 127)/128), 256, FH_SMEM>>>(
        ah_h, wlh_h, logits, Vdim, Cdim);

    loss_row_k<<<Mdim, 256>>>(logits, target);
    if (has_loss)
        loss_reduce_k<<<1, 256>>>(out);
}

// round 7
// speedup vs baseline: 3.4002x; 1.0825x over previous
#include <cuda_runtime.h>
#include <cuda_bf16.h>
#include <cuda_fp16.h>
#include <cstdint>
#include <math.h>

#define Bdim 2
#define Tdim 2048
#define Cdim 768
#define Hdim 12
#define Ddim 64
#define Ldim 6
#define Vdim 50257
#define Mdim (Bdim*Tdim)      /* 4096 */
#define C3   (3*Cdim)         /* 2304 */
#define Fdim (4*Cdim)         /* 3072 */

// ===================== device scratch (no allocations) ======================
__device__ float g_h  [Mdim*Cdim];
__device__ float g_rowloss[Mdim];

__device__ __nv_bfloat16 g_wqkv_hi[Ldim*C3*Cdim],  g_wqkv_lo[Ldim*C3*Cdim];
__device__ __nv_bfloat16 g_wff1_hi[Ldim*Fdim*Cdim], g_wff1_lo[Ldim*Fdim*Cdim];
__device__ __nv_bfloat16 g_wff2_hi[Ldim*Cdim*Fdim], g_wff2_lo[Ldim*Cdim*Fdim];
__device__ __half        g_wlm_h[(size_t)Vdim*Cdim];
__device__ __nv_bfloat16 g_xn_hi[Mdim*Cdim],  g_xn_lo[Mdim*Cdim];
__device__ __nv_bfloat16 g_ffh_hi[Mdim*Fdim], g_ffh_lo[Mdim*Fdim];
__device__ __half        g_ah_h[Mdim*Cdim];
__device__ __nv_bfloat16 g_qkv_hi[Mdim*C3],   g_qkv_lo[Mdim*C3];

// ===================== asm helpers (baseline sm_80+ ISA) ====================
__device__ __forceinline__ uint32_t smem_to_u32(const void* p) {
    uint32_t a;
    asm("{ .reg .u64 t; cvta.to.shared.u64 t, %1; cvt.u32.u64 %0, t; }" : "=r"(a) : "l"(p));
    return a;
}
__device__ __forceinline__ void cp_async16(uint32_t dst, const void* src){
    asm volatile("cp.async.cg.shared.global [%0], [%1], 16;" :: "r"(dst), "l"(src));
}
#define CP_COMMIT() asm volatile("cp.async.commit_group;" ::: "memory")
#define CP_WAIT0()  asm volatile("cp.async.wait_group 0;" ::: "memory")

__device__ __forceinline__ void ldsm_x4(uint32_t* r, uint32_t addr){
    asm volatile("ldmatrix.sync.aligned.m8n8.x4.shared.b16 {%0,%1,%2,%3}, [%4];"
        : "=r"(r[0]), "=r"(r[1]), "=r"(r[2]), "=r"(r[3]) : "r"(addr));
}
__device__ __forceinline__ void ldsm_x4_t(uint32_t* r, uint32_t addr){
    asm volatile("ldmatrix.sync.aligned.m8n8.x4.trans.shared.b16 {%0,%1,%2,%3}, [%4];"
        : "=r"(r[0]), "=r"(r[1]), "=r"(r[2]), "=r"(r[3]) : "r"(addr));
}
__device__ __forceinline__ void mma_bf16(float* d, const uint32_t* a,
                                         uint32_t b0, uint32_t b1){
    asm volatile("mma.sync.aligned.m16n8k16.row.col.f32.bf16.bf16.f32 "
        "{%0,%1,%2,%3}, {%4,%5,%6,%7}, {%8,%9}, {%0,%1,%2,%3};"
        : "+f"(d[0]), "+f"(d[1]), "+f"(d[2]), "+f"(d[3])
        : "r"(a[0]), "r"(a[1]), "r"(a[2]), "r"(a[3]), "r"(b0), "r"(b1));
}
__device__ __forceinline__ void mma_f16(float* d, const uint32_t* a,
                                        uint32_t b0, uint32_t b1){
    asm volatile("mma.sync.aligned.m16n8k16.row.col.f32.f16.f16.f32 "
        "{%0,%1,%2,%3}, {%4,%5,%6,%7}, {%8,%9}, {%0,%1,%2,%3};"
        : "+f"(d[0]), "+f"(d[1]), "+f"(d[2]), "+f"(d[3])
        : "r"(a[0]), "r"(a[1]), "r"(a[2]), "r"(a[3]), "r"(b0), "r"(b1));
}
__device__ __forceinline__ uint32_t pack_bf16x2(float lo, float hi){
    uint32_t r;
    asm("cvt.rn.bf16x2.f32 %0, %1, %2;" : "=r"(r) : "f"(hi), "f"(lo));
    return r;
}

// ===================== reductions ===========================================
__device__ __forceinline__ float blockReduceMax(float v){
    __shared__ float sh[8];
    int lid = threadIdx.x & 31, wid = threadIdx.x >> 5;
    #pragma unroll
    for (int o = 16; o > 0; o >>= 1) v = fmaxf(v, __shfl_xor_sync(0xffffffffu, v, o));
    if (lid == 0) sh[wid] = v;
    __syncthreads();
    v = sh[lid & 7];
    #pragma unroll
    for (int o = 4; o > 0; o >>= 1) v = fmaxf(v, __shfl_xor_sync(0xffffffffu, v, o));
    __syncthreads();
    return v;
}
__device__ __forceinline__ float blockReduceSum(float v){
    __shared__ float sh[8];
    int lid = threadIdx.x & 31, wid = threadIdx.x >> 5;
    #pragma unroll
    for (int o = 16; o > 0; o >>= 1) v += __shfl_xor_sync(0xffffffffu, v, o);
    if (lid == 0) sh[wid] = v;
    __syncthreads();
    v = sh[lid & 7];
    #pragma unroll
    for (int o = 4; o > 0; o >>= 1) v += __shfl_xor_sync(0xffffffffu, v, o);
    __syncthreads();
    return v;
}

// ===================== small kernels ========================================
__global__ void embed_k(const int* __restrict__ x,
                        const float* __restrict__ wte,
                        const float* __restrict__ wpe){
    int i = blockIdx.x * blockDim.x + threadIdx.x;
    if (i >= Mdim * Cdim) return;
    int c  = i % Cdim;
    int bt = i / Cdim;
    int t  = bt % Tdim;
    g_h[i] = wte[(size_t)x[bt] * Cdim + c] + wpe[(size_t)t * Cdim + c];
}

// n must be a multiple of 4
__global__ void cvt_k(const float* __restrict__ in, __nv_bfloat16* __restrict__ hi,
                      __nv_bfloat16* __restrict__ lo, long n){
    long stride = (long)gridDim.x * blockDim.x * 4;
    for (long i = ((long)blockIdx.x * blockDim.x + threadIdx.x) * 4; i < n; i += stride){
        float4 v = *(const float4*)(in + i);
        __nv_bfloat16 h0 = __float2bfloat16(v.x), h1 = __float2bfloat16(v.y);
        __nv_bfloat16 h2 = __float2bfloat16(v.z), h3 = __float2bfloat16(v.w);
        uint2 hw, lw;
        hw.x = (uint32_t)__bfloat16_as_ushort(h0) | ((uint32_t)__bfloat16_as_ushort(h1) << 16);
        hw.y = (uint32_t)__bfloat16_as_ushort(h2) | ((uint32_t)__bfloat16_as_ushort(h3) << 16);
        lw.x = pack_bf16x2(v.x - __bfloat162float(h0), v.y - __bfloat162float(h1));
        lw.y = pack_bf16x2(v.z - __bfloat162float(h2), v.w - __bfloat162float(h3));
        *(uint2*)(hi + i) = hw;
        *(uint2*)(lo + i) = lw;
    }
}

__global__ void cvt_h_k(const float* __restrict__ in, __half* __restrict__ o, long n){
    long stride = (long)gridDim.x * blockDim.x * 4;
    for (long i = ((long)blockIdx.x * blockDim.x + threadIdx.x) * 4; i < n; i += stride){
        float4 v = *(const float4*)(in + i);
        __half2 a = __floats2half2_rn(v.x, v.y);
        __half2 b = __floats2half2_rn(v.z, v.w);
        uint2 w;
        w.x = *(uint32_t*)&a;
        w.y = *(uint32_t*)&b;
        *(uint2*)(o + i) = w;
    }
}

__global__ void ln_k(const float* __restrict__ in,
                     const float* __restrict__ w,
                     const float* __restrict__ b,
                     __nv_bfloat16* __restrict__ ohi,
                     __nv_bfloat16* __restrict__ olo){
    int row = blockIdx.x, tid = threadIdx.x;
    const float* xp = in + (size_t)row * Cdim;
    float v[3], s = 0.f, ss = 0.f;
    #pragma unroll
    for (int i = 0; i < 3; i++){
        v[i] = xp[tid + i * 256];
        s += v[i]; ss += v[i] * v[i];
    }
    s  = blockReduceSum(s);
    ss = blockReduceSum(ss);
    float mean = s * (1.f / Cdim);
    float var  = ss * (1.f / Cdim) - mean * mean;
    float rstd = rsqrtf(var + 1e-5f);
    #pragma unroll
    for (int i = 0; i < 3; i++){
        int c = tid + i * 256;
        float y = (v[i] - mean) * rstd * w[c] + b[c];
        __nv_bfloat16 h = __float2bfloat16(y);
        ohi[(size_t)row * Cdim + c] = h;
        olo[(size_t)row * Cdim + c] = __float2bfloat16(y - __bfloat162float(h));
    }
}

// ===================== tensor-core split-bf16 GEMM (mma.sync) ===============
// N must be a multiple of 128. Supports split-K via gridDim.z (mode 2 only).
// modes: 1: relu(acc+bias)->hi/lo | 2: out_f atomicAdd(acc[+bias if z==0]) | 4: (acc+bias)->hi/lo
#define MAT_B   10240            /* 128 rows * 80 bytes */
#define STG_B   (4*MAT_B)
#define GT_SMEM (2*STG_B)        /* 81920 bytes */

__global__ __launch_bounds__(256, 2) void gemm_tc_k(
        const __nv_bfloat16* __restrict__ Ahi, const __nv_bfloat16* __restrict__ Alo,
        const __nv_bfloat16* __restrict__ Bhi, const __nv_bfloat16* __restrict__ Blo,
        const float* __restrict__ bias,
        float* __restrict__ out_f,
        __nv_bfloat16* __restrict__ out_hi, __nv_bfloat16* __restrict__ out_lo,
        int N, int K, int mode){
    extern __shared__ char smem[];
    uint32_t sbase = smem_to_u32(smem);
    int tid = threadIdx.x, wid = tid >> 5, lane = tid & 31;
    int warpRow = wid >> 2, warpCol = wid & 3;

    long row0 = (long)blockIdx.x * 128;
    long n0   = (long)blockIdx.y * 128;
    int kspan = K / (int)gridDim.z;
    long kbase = (long)blockIdx.z * kspan;
    int nIter = kspan >> 5;

    float acc[4][4][4];
    #pragma unroll
    for (int i = 0; i < 4; i++)
        #pragma unroll
        for (int j = 0; j < 4; j++)
            #pragma unroll
            for (int q = 0; q < 4; q++) acc[i][j][q] = 0.f;

    auto issue = [&](int it){
        if (it >= nIter) return;
        long k0 = kbase + ((long)it << 5);
        uint32_t stg = sbase + (uint32_t)(it & 1) * STG_B;
        #pragma unroll
        for (int j = 0; j < 8; j++){
            int c   = tid + j * 256;
            int mat = c >> 9;
            int id  = c & 511;
            int row = id >> 2;
            int c8  = (id & 3) << 3;
            const __nv_bfloat16* src;
            if (mat < 2){
                src = (mat == 0 ? Ahi : Alo) + (row0 + row) * (long)K + k0 + c8;
            } else {
                src = (mat == 2 ? Bhi : Blo) + (n0 + row) * (long)K + k0 + c8;
            }
            uint32_t dst = stg + (uint32_t)(mat * MAT_B + row * 80 + c8 * 2);
            cp_async16(dst, src);
        }
        CP_COMMIT();
    };

    issue(0);
    for (int it = 0; it < nIter; it++){
        CP_WAIT0();
        __syncthreads();        // data(it) visible + all warps done with compute(it-1)
        issue(it + 1);          // safely overwrites buffer of it-1

        uint32_t stg = sbase + (uint32_t)(it & 1) * STG_B;
        uint32_t aHi = stg;
        uint32_t aLo = stg + MAT_B;
        uint32_t bHi = stg + 2*MAT_B;
        uint32_t bLo = stg + 3*MAT_B;
        uint32_t rsel = (uint32_t)(lane & 15) * 80 + (uint32_t)(lane >> 4) * 16;

        #pragma unroll
        for (int ks = 0; ks < 32; ks += 16){
            uint32_t bh[2][4], bl[2][4];
            #pragma unroll
            for (int nj = 0; nj < 2; nj++){
                uint32_t off = (uint32_t)((warpCol*32 + nj*16) * 80 + ks*2) + rsel;
                ldsm_x4(bh[nj], bHi + off);
                ldsm_x4(bl[nj], bLo + off);
            }
            #pragma unroll
            for (int mi = 0; mi < 4; mi++){
                uint32_t ah[4], al[4];
                uint32_t off = (uint32_t)((warpRow*64 + mi*16) * 80 + ks*2) + rsel;
                ldsm_x4(ah, aHi + off);
                ldsm_x4(al, aLo + off);
                #pragma unroll
                for (int ni = 0; ni < 4; ni++){
                    int nj = ni >> 1, w = ni & 1;
                    mma_bf16(acc[mi][ni], ah, bh[nj][w], bh[nj][w+2]);
                    mma_bf16(acc[mi][ni], ah, bl[nj][w], bl[nj][w+2]);
                    mma_bf16(acc[mi][ni], al, bh[nj][w], bh[nj][w+2]);
                }
            }
        }
    }
    __syncthreads();

    bool addBias = (blockIdx.z == 0);
    #pragma unroll
    for (int mi = 0; mi < 4; mi++){
        long r0 = row0 + warpRow*64 + mi*16 + (lane >> 2);
        #pragma unroll
        for (int ni = 0; ni < 4; ni++){
            long c0 = n0 + warpCol*32 + ni*8 + (lane & 3)*2;
            float b0 = addBias ? bias[c0]     : 0.f;
            float b1 = addBias ? bias[c0 + 1] : 0.f;
            #pragma unroll
            for (int half = 0; half < 2; half++){
                long r  = r0 + half*8;
                long oi = r * (long)N + c0;
                float v0 = acc[mi][ni][half*2]     + b0;
                float v1 = acc[mi][ni][half*2 + 1] + b1;
                if (mode == 2){
                    atomicAdd(out_f + oi,     v0);
                    atomicAdd(out_f + oi + 1, v1);
                } else {
                    if (mode == 1){
                        v0 = fmaxf(v0, 0.f);
                        v1 = fmaxf(v1, 0.f);
                    }
                    float h0 = __bfloat162float(__float2bfloat16(v0));
                    float h1 = __bfloat162float(__float2bfloat16(v1));
                    *(uint32_t*)(out_hi + oi) = pack_bf16x2(v0, v1);
                    *(uint32_t*)(out_lo + oi) = pack_bf16x2(v0 - h0, v1 - h1);
                }
            }
        }
    }
}

// ===================== fp16 single-term GEMM (lm_head) ======================
#define FH_MAT  10240
#define FH_STG  (2*FH_MAT)
#define FH_SMEM (2*FH_STG)       /* 40960 */

__global__ __launch_bounds__(256, 2) void gemm_f16_k(
        const __half* __restrict__ A, const __half* __restrict__ Bm,
        float* __restrict__ out_f, int N, int K){
    extern __shared__ char smem[];
    uint32_t sbase = smem_to_u32(smem);
    int tid = threadIdx.x, wid = tid >> 5, lane = tid & 31;
    int warpRow = wid >> 2, warpCol = wid & 3;

    long row0 = (long)blockIdx.x * 128;
    long n0   = (long)blockIdx.y * 128;
    int nIter = K >> 5;

    float acc[4][4][4];
    #pragma unroll
    for (int i = 0; i < 4; i++)
        #pragma unroll
        for (int j = 0; j < 4; j++)
            #pragma unroll
            for (int q = 0; q < 4; q++) acc[i][j][q] = 0.f;

    auto issue = [&](int it){
        if (it >= nIter) return;
        int k0 = it << 5;
        uint32_t stg = sbase + (uint32_t)(it & 1) * FH_STG;
        #pragma unroll
        for (int j = 0; j < 4; j++){
            int c   = tid + j * 256;
            int mat = c >> 9;
            int id  = c & 511;
            int row = id >> 2;
            int c8  = (id & 3) << 3;
            const __half* src;
            if (mat == 0){
                src = A + (row0 + row) * (long)K + k0 + c8;
            } else {
                long br = n0 + row; if (br >= N) br = 0;
                src = Bm + br * (long)K + k0 + c8;
            }
            uint32_t dst = stg + (uint32_t)(mat * FH_MAT + row * 80 + c8 * 2);
            cp_async16(dst, src);
        }
        CP_COMMIT();
    };

    issue(0);
    for (int it = 0; it < nIter; it++){
        CP_WAIT0();
        __syncthreads();
        issue(it + 1);

        uint32_t stg = sbase + (uint32_t)(it & 1) * FH_STG;
        uint32_t aS = stg;
        uint32_t bS = stg + FH_MAT;
        uint32_t rsel = (uint32_t)(lane & 15) * 80 + (uint32_t)(lane >> 4) * 16;

        #pragma unroll
        for (int ks = 0; ks < 32; ks += 16){
            uint32_t bf[2][4];
            #pragma unroll
            for (int nj = 0; nj < 2; nj++){
                uint32_t off = (uint32_t)((warpCol*32 + nj*16) * 80 + ks*2) + rsel;
                ldsm_x4(bf[nj], bS + off);
            }
            #pragma unroll
            for (int mi = 0; mi < 4; mi++){
                uint32_t af[4];
                uint32_t off = (uint32_t)((warpRow*64 + mi*16) * 80 + ks*2) + rsel;
                ldsm_x4(af, aS + off);
                #pragma unroll
                for (int ni = 0; ni < 4; ni++){
                    int nj = ni >> 1, w = ni & 1;
                    mma_f16(acc[mi][ni], af, bf[nj][w], bf[nj][w+2]);
                }
            }
        }
    }

    // scalar stores: logits base pointer may be only 4B-aligned (out+1)
    #pragma unroll
    for (int mi = 0; mi < 4; mi++){
        long r0 = row0 + warpRow*64 + mi*16 + (lane >> 2);
        #pragma unroll
        for (int ni = 0; ni < 4; ni++){
            long c0 = n0 + warpCol*32 + ni*8 + (lane & 3)*2;
            #pragma unroll
            for (int half = 0; half < 2; half++){
                long r = r0 + half*8;
                #pragma unroll
                for (int e = 0; e < 2; e++){
                    long n = c0 + e;
                    if (n < N)
                        out_f[r * (long)N + n] = acc[mi][ni][half*2 + e];
                }
            }
        }
    }
}

// ===================== flash attention (bf16 mma, hi/lo split) ==============
#define FA_QB    (128*144)
#define FA_KVMAT (64*144)
#define FA_STGB  (4*FA_KVMAT)
#define FA_SMEM  (2*FA_QB + 2*FA_STGB)   /* 110592 */

__global__ __launch_bounds__(256, 2) void flash_k(
        const __nv_bfloat16* __restrict__ qkvh,
        const __nv_bfloat16* __restrict__ qkvl){
    extern __shared__ char smem[];
    uint32_t sb = smem_to_u32(smem);
    uint32_t Qh = sb, Ql = sb + FA_QB;
    uint32_t kvb = sb + 2*FA_QB;

    int tid = threadIdx.x, wid = tid >> 5, lane = tid & 31;
    int g = lane >> 2, tq = lane & 3;
    int qb = (int)gridDim.x - 1 - (int)blockIdx.x;
    int bh = blockIdx.y; int bq = bh / Hdim, head = bh % Hdim;
    int q0 = qb * 128;
    long rowbase = (long)bq * Tdim;

    #pragma unroll
    for (int j = 0; j < 8; j++){
        int id = tid + j*256;
        int mat = id >> 10, rem = id & 1023;
        int row = rem >> 3, c8 = (rem & 7) << 3;
        const __nv_bfloat16* src = (mat ? qkvl : qkvh)
            + (rowbase + q0 + row)*(long)C3 + head*Ddim + c8;
        cp_async16((mat ? Ql : Qh) + (uint32_t)(row*144 + c8*2), src);
    }

    int nkv = 2*qb + 2;
    auto issue = [&](int j){
        if (j >= nkv) return;
        int s0 = j * 64;
        uint32_t stg = kvb + (uint32_t)(j & 1) * FA_STGB;
        #pragma unroll
        for (int jj = 0; jj < 8; jj++){
            int id = tid + jj*256;
            int mat = id >> 9, rem = id & 511;
            int row = rem >> 3, c8 = (rem & 7) << 3;
            const __nv_bfloat16* base = (mat & 1) ? qkvl : qkvh;
            int coff = (mat < 2) ? Cdim : 2*Cdim;
            const __nv_bfloat16* src = base
                + (rowbase + s0 + row)*(long)C3 + coff + head*Ddim + c8;
            cp_async16(stg + (uint32_t)(mat*FA_KVMAT + row*144 + c8*2), src);
        }
        CP_COMMIT();
    };

    float mrow[2] = {-1e30f, -1e30f};
    float lrow[2] = {0.f, 0.f};
    float oacc[8][4];
    #pragma unroll
    for (int i = 0; i < 8; i++)
        #pragma unroll
        for (int e = 0; e < 4; e++) oacc[i][e] = 0.f;

    int t0w = q0 + wid*16;
    uint32_t rsel16 = (uint32_t)(lane & 15)*144 + (uint32_t)(lane >> 4)*16;
    int vtsel = lane >> 3, vrt = lane & 7;
    uint32_t vrow_off = ((vtsel >> 1) ? 8u : 0u) + (uint32_t)vrt;
    uint32_t vcol_off = (vtsel & 1) ? 16u : 0u;

    issue(0);
    for (int j = 0; j < nkv; j++){
        CP_WAIT0();
        __syncthreads();        // data(j) visible + all warps done with compute(j-1)
        issue(j + 1);

        int s0 = j * 64;
        if (s0 <= t0w + 15){
            uint32_t stg = kvb + (uint32_t)(j & 1) * FA_STGB;
            uint32_t Kh = stg, Kl = stg + FA_KVMAT;
            uint32_t Vh = stg + 2*FA_KVMAT, Vl = stg + 3*FA_KVMAT;

            float S[8][4];
            #pragma unroll
            for (int i = 0; i < 8; i++)
                #pragma unroll
                for (int e = 0; e < 4; e++) S[i][e] = 0.f;

            #pragma unroll
            for (int dc = 0; dc < 4; dc++){
                uint32_t aoff = (uint32_t)(wid*16)*144 + (uint32_t)dc*32 + rsel16;
                uint32_t ah[4], al[4];
                ldsm_x4(ah, Qh + aoff);
                ldsm_x4(al, Ql + aoff);
                #pragma unroll
                for (int ng = 0; ng < 4; ng++){
                    uint32_t boff = (uint32_t)(ng*16)*144 + (uint32_t)dc*32 + rsel16;
                    uint32_t kh[4], kl[4];
                    ldsm_x4(kh, Kh + boff);
                    ldsm_x4(kl, Kl + boff);
                    #pragma unroll
                    for (int w = 0; w < 2; w++){
                        mma_bf16(S[ng*2+w], ah, kh[w], kh[w+2]);
                        mma_bf16(S[ng*2+w], ah, kl[w], kl[w+2]);
                        mma_bf16(S[ng*2+w], al, kh[w], kh[w+2]);
                    }
                }
            }

            bool needMask = (s0 + 63 > t0w);
            #pragma unroll
            for (int ns = 0; ns < 8; ns++)
                #pragma unroll
                for (int e = 0; e < 4; e++){
                    float v = S[ns][e] * 0.125f;
                    if (needMask){
                        int t = t0w + g + (e >> 1)*8;
                        int s = s0 + ns*8 + tq*2 + (e & 1);
                        if (s > t) v = -1e30f;
                    }
                    S[ns][e] = v;
                }

            #pragma unroll
            for (int r = 0; r < 2; r++){
                float mx = -1e30f;
                #pragma unroll
                for (int ns = 0; ns < 8; ns++)
                    mx = fmaxf(mx, fmaxf(S[ns][r*2], S[ns][r*2+1]));
                mx = fmaxf(mx, __shfl_xor_sync(0xffffffffu, mx, 1));
                mx = fmaxf(mx, __shfl_xor_sync(0xffffffffu, mx, 2));
                float mnew = fmaxf(mrow[r], mx);
                float corr = __expf(mrow[r] - mnew);
                mrow[r] = mnew;
                float lsum = 0.f;
                #pragma unroll
                for (int ns = 0; ns < 8; ns++){
                    float p0 = __expf(S[ns][r*2]   - mnew);
                    float p1 = __expf(S[ns][r*2+1] - mnew);
                    S[ns][r*2] = p0; S[ns][r*2+1] = p1;
                    lsum += p0 + p1;
                }
                lsum += __shfl_xor_sync(0xffffffffu, lsum, 1);
                lsum += __shfl_xor_sync(0xffffffffu, lsum, 2);
                lrow[r] = lrow[r]*corr + lsum;
                #pragma unroll
                for (int dt = 0; dt < 8; dt++){
                    oacc[dt][r*2]   *= corr;
                    oacc[dt][r*2+1] *= corr;
                }
            }

            #pragma unroll
            for (int sc = 0; sc < 4; sc++){
                uint32_t ph[4], pl[4];
                #pragma unroll
                for (int half = 0; half < 2; half++){
                    int ns = sc*2 + half;
                    float v0 = S[ns][0], v1 = S[ns][1], v2 = S[ns][2], v3 = S[ns][3];
                    float h0 = __bfloat162float(__float2bfloat16(v0));
                    float h1 = __bfloat162float(__float2bfloat16(v1));
                    float h2 = __bfloat162float(__float2bfloat16(v2));
                    float h3 = __bfloat162float(__float2bfloat16(v3));
                    ph[half*2+0] = pack_bf16x2(v0, v1);
                    ph[half*2+1] = pack_bf16x2(v2, v3);
                    pl[half*2+0] = pack_bf16x2(v0 - h0, v1 - h1);
                    pl[half*2+1] = pack_bf16x2(v2 - h2, v3 - h3);
                }
                uint32_t vbase = (uint32_t)((sc*16 + vrow_off)*144) + vcol_off;
                #pragma unroll
                for (int dg = 0; dg < 4; dg++){
                    uint32_t vh_[4], vl_[4];
                    ldsm_x4_t(vh_, Vh + vbase + (uint32_t)dg*32);
                    ldsm_x4_t(vl_, Vl + vbase + (uint32_t)dg*32);
                    #pragma unroll
                    for (int w = 0; w < 2; w++){
                        int dt = dg*2 + w;
                        mma_bf16(oacc[dt], ph, vh_[w], vh_[w+2]);
                        mma_bf16(oacc[dt], ph, vl_[w], vl_[w+2]);
                        mma_bf16(oacc[dt], pl, vh_[w], vh_[w+2]);
                    }
                }
            }
        }
    }

    #pragma unroll
    for (int r = 0; r < 2; r++){
        float inv = 1.f / lrow[r];
        long t = (long)t0w + g + r*8;
        float* hp = g_h + (rowbase + t)*(long)Cdim + head*Ddim;
        #pragma unroll
        for (int dt = 0; dt < 8; dt++){
            float2* p = (float2*)(hp + dt*8 + tq*2);
            float2 v = *p;
            v.x += oacc[dt][r*2]   * inv;
            v.y += oacc[dt][r*2+1] * inv;
            *p = v;
        }
    }
}

// ===================== cross-entropy (single-pass online) ===================
__global__ void loss_row_k(const float* __restrict__ logits,
                           const int* __restrict__ target){
    int row = blockIdx.x, tid = threadIdx.x;
    const float* p = logits + (size_t)row * Vdim;
    float m = -1e30f, s = 0.f;
    for (int i = tid; i < Vdim; i += 256){
        float x = p[i];
        if (x > m){
            s = s * __expf(m - x) + 1.f;
            m = x;
        } else {
            s += __expf(x - m);
        }
    }
    float mg = blockReduceMax(m);
    s *= __expf(m - mg);
    float tot = blockReduceSum(s);
    if (tid == 0){
        float lse = logf(tot) + mg;
        g_rowloss[row] = lse - p[target[row]];
    }
}
__global__ void loss_reduce_k(float* out){
    float s = 0.f;
    for (int i = threadIdx.x; i < Mdim; i += 256) s += g_rowloss[i];
    s = blockReduceSum(s);
    if (threadIdx.x == 0) out[0] = s / (float)Mdim;
}

// ===================== launch ===============================================
extern "C" void kernel_launch(void* const* d_in, const int* in_sizes, int n_in,
                              void* d_out, int out_size){
    const int*   x      = (const int*)  d_in[0];
    const int*   target = (const int*)  d_in[1];
    const float* wte    = (const float*)d_in[2];
    const float* wpe    = (const float*)d_in[3];
    const float* ln1_w  = (const float*)d_in[4];
    const float* ln1_b  = (const float*)d_in[5];
    const float* attn_w = (const float*)d_in[6];
    const float* attn_b = (const float*)d_in[7];
    const float* ln2_w  = (const float*)d_in[8];
    const float* ln2_b  = (const float*)d_in[9];
    const float* ff1_w  = (const float*)d_in[10];
    const float* ff1_b  = (const float*)d_in[11];
    const float* ff2_w  = (const float*)d_in[12];
    const float* ff2_b  = (const float*)d_in[13];
    const float* lm_w   = (const float*)d_in[14];

    float* out = (float*)d_out;
    bool has_loss = ((long long)out_size == (long long)Mdim * Vdim + 1);
    float* logits = has_loss ? out + 1 : out;

    cudaFuncSetAttribute(gemm_tc_k,  cudaFuncAttributeMaxDynamicSharedMemorySize, GT_SMEM);
    cudaFuncSetAttribute(gemm_f16_k, cudaFuncAttributeMaxDynamicSharedMemorySize, FH_SMEM);
    cudaFuncSetAttribute(flash_k,    cudaFuncAttributeMaxDynamicSharedMemorySize, FA_SMEM);

    float* ph;
    cudaGetSymbolAddress((void**)&ph, g_h);
    __nv_bfloat16 *wqh,*wql,*wf1h,*wf1l,*wf2h,*wf2l;
    __nv_bfloat16 *xnh,*xnl,*fhh,*fhl,*qvh,*qvl;
    __half *wlh_h, *ah_h;
    cudaGetSymbolAddress((void**)&wqh,  g_wqkv_hi);  cudaGetSymbolAddress((void**)&wql,  g_wqkv_lo);
    cudaGetSymbolAddress((void**)&wf1h, g_wff1_hi);  cudaGetSymbolAddress((void**)&wf1l, g_wff1_lo);
    cudaGetSymbolAddress((void**)&wf2h, g_wff2_hi);  cudaGetSymbolAddress((void**)&wf2l, g_wff2_lo);
    cudaGetSymbolAddress((void**)&wlh_h, g_wlm_h);
    cudaGetSymbolAddress((void**)&xnh,  g_xn_hi);    cudaGetSymbolAddress((void**)&xnl,  g_xn_lo);
    cudaGetSymbolAddress((void**)&fhh,  g_ffh_hi);   cudaGetSymbolAddress((void**)&fhl,  g_ffh_lo);
    cudaGetSymbolAddress((void**)&ah_h, g_ah_h);
    cudaGetSymbolAddress((void**)&qvh,  g_qkv_hi);   cudaGetSymbolAddress((void**)&qvl,  g_qkv_lo);

    cvt_k<<<2048, 256>>>(attn_w, wqh,  wql,  (long)Ldim*C3*Cdim);
    cvt_k<<<2048, 256>>>(ff1_w,  wf1h, wf1l, (long)Ldim*Fdim*Cdim);
    cvt_k<<<2048, 256>>>(ff2_w,  wf2h, wf2l, (long)Ldim*Cdim*Fdim);
    cvt_h_k<<<4096, 256>>>(lm_w, wlh_h, (long)Vdim*Cdim);

    embed_k<<<(Mdim*Cdim + 255)/256, 256>>>(x, wte, wpe);

    for (int l = 0; l < Ldim; l++){
        ln_k<<<Mdim, 256>>>(ph, ln1_w + (size_t)l*Cdim, ln1_b + (size_t)l*Cdim, xnh, xnl);

        gemm_tc_k<<<dim3(Mdim/128, C3/128, 1), 256, GT_SMEM>>>(
            xnh, xnl, wqh + (size_t)l*C3*Cdim, wql + (size_t)l*C3*Cdim,
            attn_b + (size_t)l*C3, nullptr, qvh, qvl, C3, Cdim, 4);

        flash_k<<<dim3(Tdim/128, Bdim*Hdim), 256, FA_SMEM>>>(qvh, qvl);

        ln_k<<<Mdim, 256>>>(ph, ln2_w + (size_t)l*Cdim, ln2_b + (size_t)l*Cdim, xnh, xnl);

        gemm_tc_k<<<dim3(Mdim/128, Fdim/128, 1), 256, GT_SMEM>>>(
            xnh, xnl, wf1h + (size_t)l*Fdim*Cdim, wf1l + (size_t)l*Fdim*Cdim,
            ff1_b + (size_t)l*Fdim, nullptr, fhh, fhl, Fdim, Cdim, 1);

        // split-K x2: 384 CTAs instead of 192 (fills the 296 resident slots)
        gemm_tc_k<<<dim3(Mdim/128, Cdim/128, 2), 256, GT_SMEM>>>(
            fhh, fhl, wf2h + (size_t)l*Cdim*Fdim, wf2l + (size_t)l*Cdim*Fdim,
            ff2_b + (size_t)l*Cdim, ph, nullptr, nullptr, Cdim, Fdim, 2);
    }

    cvt_h_k<<<2048, 256>>>(ph, ah_h, (long)Mdim*Cdim);

    gemm_f16_k<<<dim3(Mdim/128, (Vdim + 127)/128), 256, FH_SMEM>>>(
        ah_h, wlh_h, logits, Vdim, Cdim);

    loss_row_k<<<Mdim, 256>>>(logits, target);
    if (has_loss)
        loss_reduce_k<<<1, 256>>>(out);
}

// round 8
// speedup vs baseline: 3.9692x; 1.1673x over previous
#include <cuda_runtime.h>
#include <cuda_bf16.h>
#include <cuda_fp16.h>
#include <cstdint>
#include <math.h>

#define Bdim 2
#define Tdim 2048
#define Cdim 768
#define Hdim 12
#define Ddim 64
#define Ldim 6
#define Vdim 50257
#define Mdim (Bdim*Tdim)      /* 4096 */
#define C3   (3*Cdim)         /* 2304 */
#define Fdim (4*Cdim)         /* 3072 */

// ===================== device scratch (no allocations) ======================
__device__ float g_h  [Mdim*Cdim];
__device__ float g_rowloss[Mdim];

__device__ __half g_wqkv_h[Ldim*C3*Cdim];
__device__ __half g_wff1_h[Ldim*Fdim*Cdim];
__device__ __half g_wff2_h[Ldim*Cdim*Fdim];
__device__ __half g_wlm_h[(size_t)Vdim*Cdim];
__device__ __half g_xn_hi[Mdim*Cdim],  g_xn_lo[Mdim*Cdim];
__device__ __half g_ffh_hi[Mdim*Fdim], g_ffh_lo[Mdim*Fdim];
__device__ __half g_ah_h[Mdim*Cdim];
__device__ __half g_qkv_hi[Mdim*C3],   g_qkv_lo[Mdim*C3];

// ===================== asm helpers (baseline sm_80+ ISA) ====================
__device__ __forceinline__ uint32_t smem_to_u32(const void* p) {
    uint32_t a;
    asm("{ .reg .u64 t; cvta.to.shared.u64 t, %1; cvt.u32.u64 %0, t; }" : "=r"(a) : "l"(p));
    return a;
}
__device__ __forceinline__ void cp_async16(uint32_t dst, const void* src){
    asm volatile("cp.async.cg.shared.global [%0], [%1], 16;" :: "r"(dst), "l"(src));
}
#define CP_COMMIT() asm volatile("cp.async.commit_group;" ::: "memory")
#define CP_WAIT0()  asm volatile("cp.async.wait_group 0;" ::: "memory")

__device__ __forceinline__ void ldsm_x4(uint32_t* r, uint32_t addr){
    asm volatile("ldmatrix.sync.aligned.m8n8.x4.shared.b16 {%0,%1,%2,%3}, [%4];"
        : "=r"(r[0]), "=r"(r[1]), "=r"(r[2]), "=r"(r[3]) : "r"(addr));
}
__device__ __forceinline__ void ldsm_x4_t(uint32_t* r, uint32_t addr){
    asm volatile("ldmatrix.sync.aligned.m8n8.x4.trans.shared.b16 {%0,%1,%2,%3}, [%4];"
        : "=r"(r[0]), "=r"(r[1]), "=r"(r[2]), "=r"(r[3]) : "r"(addr));
}
__device__ __forceinline__ void mma_f16(float* d, const uint32_t* a,
                                        uint32_t b0, uint32_t b1){
    asm volatile("mma.sync.aligned.m16n8k16.row.col.f32.f16.f16.f32 "
        "{%0,%1,%2,%3}, {%4,%5,%6,%7}, {%8,%9}, {%0,%1,%2,%3};"
        : "+f"(d[0]), "+f"(d[1]), "+f"(d[2]), "+f"(d[3])
        : "r"(a[0]), "r"(a[1]), "r"(a[2]), "r"(a[3]), "r"(b0), "r"(b1));
}
__device__ __forceinline__ uint32_t pack_half2(float lo, float hi){
    uint32_t r;
    asm("cvt.rn.f16x2.f32 %0, %1, %2;" : "=r"(r) : "f"(hi), "f"(lo));
    return r;
}

// ===================== reductions ===========================================
__device__ __forceinline__ float blockReduceMax(float v){
    __shared__ float sh[8];
    int lid = threadIdx.x & 31, wid = threadIdx.x >> 5;
    #pragma unroll
    for (int o = 16; o > 0; o >>= 1) v = fmaxf(v, __shfl_xor_sync(0xffffffffu, v, o));
    if (lid == 0) sh[wid] = v;
    __syncthreads();
    v = sh[lid & 7];
    #pragma unroll
    for (int o = 4; o > 0; o >>= 1) v = fmaxf(v, __shfl_xor_sync(0xffffffffu, v, o));
    __syncthreads();
    return v;
}
__device__ __forceinline__ float blockReduceSum(float v){
    __shared__ float sh[8];
    int lid = threadIdx.x & 31, wid = threadIdx.x >> 5;
    #pragma unroll
    for (int o = 16; o > 0; o >>= 1) v += __shfl_xor_sync(0xffffffffu, v, o);
    if (lid == 0) sh[wid] = v;
    __syncthreads();
    v = sh[lid & 7];
    #pragma unroll
    for (int o = 4; o > 0; o >>= 1) v += __shfl_xor_sync(0xffffffffu, v, o);
    __syncthreads();
    return v;
}

// ===================== small kernels ========================================
__global__ void embed_k(const int* __restrict__ x,
                        const float* __restrict__ wte,
                        const float* __restrict__ wpe){
    int i = blockIdx.x * blockDim.x + threadIdx.x;
    if (i >= Mdim * Cdim) return;
    int c  = i % Cdim;
    int bt = i / Cdim;
    int t  = bt % Tdim;
    g_h[i] = wte[(size_t)x[bt] * Cdim + c] + wpe[(size_t)t * Cdim + c];
}

__global__ void cvt_h_k(const float* __restrict__ in, __half* __restrict__ o, long n){
    long stride = (long)gridDim.x * blockDim.x * 4;
    for (long i = ((long)blockIdx.x * blockDim.x + threadIdx.x) * 4; i < n; i += stride){
        float4 v = *(const float4*)(in + i);
        uint2 w;
        w.x = pack_half2(v.x, v.y);
        w.y = pack_half2(v.z, v.w);
        *(uint2*)(o + i) = w;
    }
}

__global__ void ln_k(const float* __restrict__ in,
                     const float* __restrict__ w,
                     const float* __restrict__ b,
                     __half* __restrict__ ohi,
                     __half* __restrict__ olo){
    int row = blockIdx.x, tid = threadIdx.x;
    const float* xp = in + (size_t)row * Cdim;
    float v[3], s = 0.f, ss = 0.f;
    #pragma unroll
    for (int i = 0; i < 3; i++){
        v[i] = xp[tid + i * 256];
        s += v[i]; ss += v[i] * v[i];
    }
    s  = blockReduceSum(s);
    ss = blockReduceSum(ss);
    float mean = s * (1.f / Cdim);
    float var  = ss * (1.f / Cdim) - mean * mean;
    float rstd = rsqrtf(var + 1e-5f);
    #pragma unroll
    for (int i = 0; i < 3; i++){
        int c = tid + i * 256;
        float y = (v[i] - mean) * rstd * w[c] + b[c];
        __half h = __float2half_rn(y);
        ohi[(size_t)row * Cdim + c] = h;
        olo[(size_t)row * Cdim + c] = __float2half_rn(y - __half2float(h));
    }
}

// ===================== fp16 2-term split GEMM (mma.sync) ====================
// C[M,N] = (Ahi+Alo)[M,K] @ B[N,K]^T.  A hi/lo fp16, B single fp16.
// N must be a multiple of 128. Split-K via gridDim.z (mode 2 only).
// modes: 1: relu(acc+bias)->hi/lo | 2: out_f atomicAdd(acc[+bias if z==0]) | 4: (acc+bias)->hi/lo
#define MAT_B   10240            /* 128 rows * 80 bytes */
#define STG_B   (3*MAT_B)
#define GT_SMEM (2*STG_B)        /* 61440 bytes */

__global__ __launch_bounds__(256, 2) void gemm_tc_k(
        const __half* __restrict__ Ahi, const __half* __restrict__ Alo,
        const __half* __restrict__ Bm,
        const float* __restrict__ bias,
        float* __restrict__ out_f,
        __half* __restrict__ out_hi, __half* __restrict__ out_lo,
        int N, int K, int mode){
    extern __shared__ char smem[];
    uint32_t sbase = smem_to_u32(smem);
    int tid = threadIdx.x, wid = tid >> 5, lane = tid & 31;
    int warpRow = wid >> 2, warpCol = wid & 3;

    long row0 = (long)blockIdx.x * 128;
    long n0   = (long)blockIdx.y * 128;
    int kspan = K / (int)gridDim.z;
    long kbase = (long)blockIdx.z * kspan;
    int nIter = kspan >> 5;

    float acc[4][4][4];
    #pragma unroll
    for (int i = 0; i < 4; i++)
        #pragma unroll
        for (int j = 0; j < 4; j++)
            #pragma unroll
            for (int q = 0; q < 4; q++) acc[i][j][q] = 0.f;

    auto issue = [&](int it){
        if (it >= nIter) return;
        long k0 = kbase + ((long)it << 5);
        uint32_t stg = sbase + (uint32_t)(it & 1) * STG_B;
        #pragma unroll
        for (int j = 0; j < 6; j++){
            int c   = tid + j * 256;          // 0..1535
            int mat = c >> 9;                  // 0:Ahi 1:Alo 2:B
            int id  = c & 511;
            int row = id >> 2;
            int c8  = (id & 3) << 3;
            const __half* src;
            if (mat < 2){
                src = (mat == 0 ? Ahi : Alo) + (row0 + row) * (long)K + k0 + c8;
            } else {
                src = Bm + (n0 + row) * (long)K + k0 + c8;
            }
            uint32_t dst = stg + (uint32_t)(mat * MAT_B + row * 80 + c8 * 2);
            cp_async16(dst, src);
        }
        CP_COMMIT();
    };

    issue(0);
    for (int it = 0; it < nIter; it++){
        CP_WAIT0();
        __syncthreads();        // data(it) visible + all warps done with compute(it-1)
        issue(it + 1);          // safely overwrites buffer of it-1

        uint32_t stg = sbase + (uint32_t)(it & 1) * STG_B;
        uint32_t aHi = stg;
        uint32_t aLo = stg + MAT_B;
        uint32_t bS  = stg + 2*MAT_B;
        uint32_t rsel = (uint32_t)(lane & 15) * 80 + (uint32_t)(lane >> 4) * 16;

        #pragma unroll
        for (int ks = 0; ks < 32; ks += 16){
            uint32_t bf[2][4];
            #pragma unroll
            for (int nj = 0; nj < 2; nj++){
                uint32_t off = (uint32_t)((warpCol*32 + nj*16) * 80 + ks*2) + rsel;
                ldsm_x4(bf[nj], bS + off);
            }
            #pragma unroll
            for (int mi = 0; mi < 4; mi++){
                uint32_t ah[4], al[4];
                uint32_t off = (uint32_t)((warpRow*64 + mi*16) * 80 + ks*2) + rsel;
                ldsm_x4(ah, aHi + off);
                ldsm_x4(al, aLo + off);
                #pragma unroll
                for (int ni = 0; ni < 4; ni++){
                    int nj = ni >> 1, w = ni & 1;
                    mma_f16(acc[mi][ni], ah, bf[nj][w], bf[nj][w+2]);
                    mma_f16(acc[mi][ni], al, bf[nj][w], bf[nj][w+2]);
                }
            }
        }
    }
    __syncthreads();

    bool addBias = (blockIdx.z == 0);
    #pragma unroll
    for (int mi = 0; mi < 4; mi++){
        long r0 = row0 + warpRow*64 + mi*16 + (lane >> 2);
        #pragma unroll
        for (int ni = 0; ni < 4; ni++){
            long c0 = n0 + warpCol*32 + ni*8 + (lane & 3)*2;
            float b0 = addBias ? bias[c0]     : 0.f;
            float b1 = addBias ? bias[c0 + 1] : 0.f;
            #pragma unroll
            for (int half = 0; half < 2; half++){
                long r  = r0 + half*8;
                long oi = r * (long)N + c0;
                float v0 = acc[mi][ni][half*2]     + b0;
                float v1 = acc[mi][ni][half*2 + 1] + b1;
                if (mode == 2){
                    atomicAdd(out_f + oi,     v0);
                    atomicAdd(out_f + oi + 1, v1);
                } else {
                    if (mode == 1){
                        v0 = fmaxf(v0, 0.f);
                        v1 = fmaxf(v1, 0.f);
                    }
                    float h0 = __half2float(__float2half_rn(v0));
                    float h1 = __half2float(__float2half_rn(v1));
                    *(uint32_t*)(out_hi + oi) = pack_half2(v0, v1);
                    *(uint32_t*)(out_lo + oi) = pack_half2(v0 - h0, v1 - h1);
                }
            }
        }
    }
}

// ===================== fp16 single-term GEMM (lm_head) ======================
#define FH_MAT  10240
#define FH_STG  (2*FH_MAT)
#define FH_SMEM (2*FH_STG)       /* 40960 */

__global__ __launch_bounds__(256, 2) void gemm_f16_k(
        const __half* __restrict__ A, const __half* __restrict__ Bm,
        float* __restrict__ out_f, int N, int K){
    extern __shared__ char smem[];
    uint32_t sbase = smem_to_u32(smem);
    int tid = threadIdx.x, wid = tid >> 5, lane = tid & 31;
    int warpRow = wid >> 2, warpCol = wid & 3;

    long row0 = (long)blockIdx.x * 128;
    long n0   = (long)blockIdx.y * 128;
    int nIter = K >> 5;

    float acc[4][4][4];
    #pragma unroll
    for (int i = 0; i < 4; i++)
        #pragma unroll
        for (int j = 0; j < 4; j++)
            #pragma unroll
            for (int q = 0; q < 4; q++) acc[i][j][q] = 0.f;

    auto issue = [&](int it){
        if (it >= nIter) return;
        int k0 = it << 5;
        uint32_t stg = sbase + (uint32_t)(it & 1) * FH_STG;
        #pragma unroll
        for (int j = 0; j < 4; j++){
            int c   = tid + j * 256;
            int mat = c >> 9;
            int id  = c & 511;
            int row = id >> 2;
            int c8  = (id & 3) << 3;
            const __half* src;
            if (mat == 0){
                src = A + (row0 + row) * (long)K + k0 + c8;
            } else {
                long br = n0 + row; if (br >= N) br = 0;
                src = Bm + br * (long)K + k0 + c8;
            }
            uint32_t dst = stg + (uint32_t)(mat * FH_MAT + row * 80 + c8 * 2);
            cp_async16(dst, src);
        }
        CP_COMMIT();
    };

    issue(0);
    for (int it = 0; it < nIter; it++){
        CP_WAIT0();
        __syncthreads();
        issue(it + 1);

        uint32_t stg = sbase + (uint32_t)(it & 1) * FH_STG;
        uint32_t aS = stg;
        uint32_t bS = stg + FH_MAT;
        uint32_t rsel = (uint32_t)(lane & 15) * 80 + (uint32_t)(lane >> 4) * 16;

        #pragma unroll
        for (int ks = 0; ks < 32; ks += 16){
            uint32_t bf[2][4];
            #pragma unroll
            for (int nj = 0; nj < 2; nj++){
                uint32_t off = (uint32_t)((warpCol*32 + nj*16) * 80 + ks*2) + rsel;
                ldsm_x4(bf[nj], bS + off);
            }
            #pragma unroll
            for (int mi = 0; mi < 4; mi++){
                uint32_t af[4];
                uint32_t off = (uint32_t)((warpRow*64 + mi*16) * 80 + ks*2) + rsel;
                ldsm_x4(af, aS + off);
                #pragma unroll
                for (int ni = 0; ni < 4; ni++){
                    int nj = ni >> 1, w = ni & 1;
                    mma_f16(acc[mi][ni], af, bf[nj][w], bf[nj][w+2]);
                }
            }
        }
    }

    // scalar stores: logits base pointer may be only 4B-aligned (out+1)
    #pragma unroll
    for (int mi = 0; mi < 4; mi++){
        long r0 = row0 + warpRow*64 + mi*16 + (lane >> 2);
        #pragma unroll
        for (int ni = 0; ni < 4; ni++){
            long c0 = n0 + warpCol*32 + ni*8 + (lane & 3)*2;
            #pragma unroll
            for (int half = 0; half < 2; half++){
                long r = r0 + half*8;
                #pragma unroll
                for (int e = 0; e < 2; e++){
                    long n = c0 + e;
                    if (n < N)
                        out_f[r * (long)N + n] = acc[mi][ni][half*2 + e];
                }
            }
        }
    }
}

// ===================== flash attention (fp16 mma, hi/lo split) ==============
#define FA_QB    (128*144)
#define FA_KVMAT (64*144)
#define FA_STGB  (4*FA_KVMAT)
#define FA_SMEM  (2*FA_QB + 2*FA_STGB)   /* 110592 */

__global__ __launch_bounds__(256, 2) void flash_k(
        const __half* __restrict__ qkvh,
        const __half* __restrict__ qkvl){
    extern __shared__ char smem[];
    uint32_t sb = smem_to_u32(smem);
    uint32_t Qh = sb, Ql = sb + FA_QB;
    uint32_t kvb = sb + 2*FA_QB;

    int tid = threadIdx.x, wid = tid >> 5, lane = tid & 31;
    int g = lane >> 2, tq = lane & 3;
    int qb = (int)gridDim.x - 1 - (int)blockIdx.x;
    int bh = blockIdx.y; int bq = bh / Hdim, head = bh % Hdim;
    int q0 = qb * 128;
    long rowbase = (long)bq * Tdim;

    #pragma unroll
    for (int j = 0; j < 8; j++){
        int id = tid + j*256;
        int mat = id >> 10, rem = id & 1023;
        int row = rem >> 3, c8 = (rem & 7) << 3;
        const __half* src = (mat ? qkvl : qkvh)
            + (rowbase + q0 + row)*(long)C3 + head*Ddim + c8;
        cp_async16((mat ? Ql : Qh) + (uint32_t)(row*144 + c8*2), src);
    }

    int nkv = 2*qb + 2;
    auto issue = [&](int j){
        if (j >= nkv) return;
        int s0 = j * 64;
        uint32_t stg = kvb + (uint32_t)(j & 1) * FA_STGB;
        #pragma unroll
        for (int jj = 0; jj < 8; jj++){
            int id = tid + jj*256;
            int mat = id >> 9, rem = id & 511;
            int row = rem >> 3, c8 = (rem & 7) << 3;
            const __half* base = (mat & 1) ? qkvl : qkvh;
            int coff = (mat < 2) ? Cdim : 2*Cdim;
            const __half* src = base
                + (rowbase + s0 + row)*(long)C3 + coff + head*Ddim + c8;
            cp_async16(stg + (uint32_t)(mat*FA_KVMAT + row*144 + c8*2), src);
        }
        CP_COMMIT();
    };

    float mrow[2] = {-1e30f, -1e30f};
    float lrow[2] = {0.f, 0.f};
    float oacc[8][4];
    #pragma unroll
    for (int i = 0; i < 8; i++)
        #pragma unroll
        for (int e = 0; e < 4; e++) oacc[i][e] = 0.f;

    int t0w = q0 + wid*16;
    uint32_t rsel16 = (uint32_t)(lane & 15)*144 + (uint32_t)(lane >> 4)*16;
    int vtsel = lane >> 3, vrt = lane & 7;
    uint32_t vrow_off = ((vtsel >> 1) ? 8u : 0u) + (uint32_t)vrt;
    uint32_t vcol_off = (vtsel & 1) ? 16u : 0u;

    issue(0);
    for (int j = 0; j < nkv; j++){
        CP_WAIT0();
        __syncthreads();        // data(j) visible + all warps done with compute(j-1)
        issue(j + 1);

        int s0 = j * 64;
        if (s0 <= t0w + 15){
            uint32_t stg = kvb + (uint32_t)(j & 1) * FA_STGB;
            uint32_t Kh = stg, Kl = stg + FA_KVMAT;
            uint32_t Vh = stg + 2*FA_KVMAT, Vl = stg + 3*FA_KVMAT;

            float S[8][4];
            #pragma unroll
            for (int i = 0; i < 8; i++)
                #pragma unroll
                for (int e = 0; e < 4; e++) S[i][e] = 0.f;

            #pragma unroll
            for (int dc = 0; dc < 4; dc++){
                uint32_t aoff = (uint32_t)(wid*16)*144 + (uint32_t)dc*32 + rsel16;
                uint32_t ah[4], al[4];
                ldsm_x4(ah, Qh + aoff);
                ldsm_x4(al, Ql + aoff);
                #pragma unroll
                for (int ng = 0; ng < 4; ng++){
                    uint32_t boff = (uint32_t)(ng*16)*144 + (uint32_t)dc*32 + rsel16;
                    uint32_t kh[4], kl[4];
                    ldsm_x4(kh, Kh + boff);
                    ldsm_x4(kl, Kl + boff);
                    #pragma unroll
                    for (int w = 0; w < 2; w++){
                        mma_f16(S[ng*2+w], ah, kh[w], kh[w+2]);
                        mma_f16(S[ng*2+w], ah, kl[w], kl[w+2]);
                        mma_f16(S[ng*2+w], al, kh[w], kh[w+2]);
                    }
                }
            }

            bool needMask = (s0 + 63 > t0w);
            #pragma unroll
            for (int ns = 0; ns < 8; ns++)
                #pragma unroll
                for (int e = 0; e < 4; e++){
                    float v = S[ns][e] * 0.125f;
                    if (needMask){
                        int t = t0w + g + (e >> 1)*8;
                        int s = s0 + ns*8 + tq*2 + (e & 1);
                        if (s > t) v = -1e30f;
                    }
                    S[ns][e] = v;
                }

            #pragma unroll
            for (int r = 0; r < 2; r++){
                float mx = -1e30f;
                #pragma unroll
                for (int ns = 0; ns < 8; ns++)
                    mx = fmaxf(mx, fmaxf(S[ns][r*2], S[ns][r*2+1]));
                mx = fmaxf(mx, __shfl_xor_sync(0xffffffffu, mx, 1));
                mx = fmaxf(mx, __shfl_xor_sync(0xffffffffu, mx, 2));
                float mnew = fmaxf(mrow[r], mx);
                float corr = __expf(mrow[r] - mnew);
                mrow[r] = mnew;
                float lsum = 0.f;
                #pragma unroll
                for (int ns = 0; ns < 8; ns++){
                    float p0 = __expf(S[ns][r*2]   - mnew);
                    float p1 = __expf(S[ns][r*2+1] - mnew);
                    S[ns][r*2] = p0; S[ns][r*2+1] = p1;
                    lsum += p0 + p1;
                }
                lsum += __shfl_xor_sync(0xffffffffu, lsum, 1);
                lsum += __shfl_xor_sync(0xffffffffu, lsum, 2);
                lrow[r] = lrow[r]*corr + lsum;
                #pragma unroll
                for (int dt = 0; dt < 8; dt++){
                    oacc[dt][r*2]   *= corr;
                    oacc[dt][r*2+1] *= corr;
                }
            }

            #pragma unroll
            for (int sc = 0; sc < 4; sc++){
                uint32_t ph[4], pl[4];
                #pragma unroll
                for (int half = 0; half < 2; half++){
                    int ns = sc*2 + half;
                    float v0 = S[ns][0], v1 = S[ns][1], v2 = S[ns][2], v3 = S[ns][3];
                    float h0 = __half2float(__float2half_rn(v0));
                    float h1 = __half2float(__float2half_rn(v1));
                    float h2 = __half2float(__float2half_rn(v2));
                    float h3 = __half2float(__float2half_rn(v3));
                    ph[half*2+0] = pack_half2(v0, v1);
                    ph[half*2+1] = pack_half2(v2, v3);
                    pl[half*2+0] = pack_half2(v0 - h0, v1 - h1);
                    pl[half*2+1] = pack_half2(v2 - h2, v3 - h3);
                }
                uint32_t vbase = (uint32_t)((sc*16 + vrow_off)*144) + vcol_off;
                #pragma unroll
                for (int dg = 0; dg < 4; dg++){
                    uint32_t vh_[4], vl_[4];
                    ldsm_x4_t(vh_, Vh + vbase + (uint32_t)dg*32);
                    ldsm_x4_t(vl_, Vl + vbase + (uint32_t)dg*32);
                    #pragma unroll
                    for (int w = 0; w < 2; w++){
                        int dt = dg*2 + w;
                        mma_f16(oacc[dt], ph, vh_[w], vh_[w+2]);
                        mma_f16(oacc[dt], ph, vl_[w], vl_[w+2]);
                        mma_f16(oacc[dt], pl, vh_[w], vh_[w+2]);
                    }
                }
            }
        }
    }

    #pragma unroll
    for (int r = 0; r < 2; r++){
        float inv = 1.f / lrow[r];
        long t = (long)t0w + g + r*8;
        float* hp = g_h + (rowbase + t)*(long)Cdim + head*Ddim;
        #pragma unroll
        for (int dt = 0; dt < 8; dt++){
            float2* p = (float2*)(hp + dt*8 + tq*2);
            float2 v = *p;
            v.x += oacc[dt][r*2]   * inv;
            v.y += oacc[dt][r*2+1] * inv;
            *p = v;
        }
    }
}

// ===================== cross-entropy (single-pass online) ===================
__global__ void loss_row_k(const float* __restrict__ logits,
                           const int* __restrict__ target){
    int row = blockIdx.x, tid = threadIdx.x;
    const float* p = logits + (size_t)row * Vdim;
    float m = -1e30f, s = 0.f;
    for (int i = tid; i < Vdim; i += 256){
        float x = p[i];
        if (x > m){
            s = s * __expf(m - x) + 1.f;
            m = x;
        } else {
            s += __expf(x - m);
        }
    }
    float mg = blockReduceMax(m);
    s *= __expf(m - mg);
    float tot = blockReduceSum(s);
    if (tid == 0){
        float lse = logf(tot) + mg;
        g_rowloss[row] = lse - p[target[row]];
    }
}
__global__ void loss_reduce_k(float* out){
    float s = 0.f;
    for (int i = threadIdx.x; i < Mdim; i += 256) s += g_rowloss[i];
    s = blockReduceSum(s);
    if (threadIdx.x == 0) out[0] = s / (float)Mdim;
}

// ===================== launch ===============================================
extern "C" void kernel_launch(void* const* d_in, const int* in_sizes, int n_in,
                              void* d_out, int out_size){
    const int*   x      = (const int*)  d_in[0];
    const int*   target = (const int*)  d_in[1];
    const float* wte    = (const float*)d_in[2];
    const float* wpe    = (const float*)d_in[3];
    const float* ln1_w  = (const float*)d_in[4];
    const float* ln1_b  = (const float*)d_in[5];
    const float* attn_w = (const float*)d_in[6];
    const float* attn_b = (const float*)d_in[7];
    const float* ln2_w  = (const float*)d_in[8];
    const float* ln2_b  = (const float*)d_in[9];
    const float* ff1_w  = (const float*)d_in[10];
    const float* ff1_b  = (const float*)d_in[11];
    const float* ff2_w  = (const float*)d_in[12];
    const float* ff2_b  = (const float*)d_in[13];
    const float* lm_w   = (const float*)d_in[14];

    float* out = (float*)d_out;
    bool has_loss = ((long long)out_size == (long long)Mdim * Vdim + 1);
    float* logits = has_loss ? out + 1 : out;

    cudaFuncSetAttribute(gemm_tc_k,  cudaFuncAttributeMaxDynamicSharedMemorySize, GT_SMEM);
    cudaFuncSetAttribute(gemm_f16_k, cudaFuncAttributeMaxDynamicSharedMemorySize, FH_SMEM);
    cudaFuncSetAttribute(flash_k,    cudaFuncAttributeMaxDynamicSharedMemorySize, FA_SMEM);

    float* ph;
    cudaGetSymbolAddress((void**)&ph, g_h);
    __half *wqk,*wf1,*wf2,*wlm;
    __half *xnh,*xnl,*fhh,*fhl,*qvh,*qvl,*ah_h;
    cudaGetSymbolAddress((void**)&wqk, g_wqkv_h);
    cudaGetSymbolAddress((void**)&wf1, g_wff1_h);
    cudaGetSymbolAddress((void**)&wf2, g_wff2_h);
    cudaGetSymbolAddress((void**)&wlm, g_wlm_h);
    cudaGetSymbolAddress((void**)&xnh, g_xn_hi);   cudaGetSymbolAddress((void**)&xnl, g_xn_lo);
    cudaGetSymbolAddress((void**)&fhh, g_ffh_hi);  cudaGetSymbolAddress((void**)&fhl, g_ffh_lo);
    cudaGetSymbolAddress((void**)&ah_h, g_ah_h);
    cudaGetSymbolAddress((void**)&qvh, g_qkv_hi);  cudaGetSymbolAddress((void**)&qvl, g_qkv_lo);

    cvt_h_k<<<2048, 256>>>(attn_w, wqk, (long)Ldim*C3*Cdim);
    cvt_h_k<<<2048, 256>>>(ff1_w,  wf1, (long)Ldim*Fdim*Cdim);
    cvt_h_k<<<2048, 256>>>(ff2_w,  wf2, (long)Ldim*Cdim*Fdim);
    cvt_h_k<<<4096, 256>>>(lm_w,   wlm, (long)Vdim*Cdim);

    embed_k<<<(Mdim*Cdim + 255)/256, 256>>>(x, wte, wpe);

    for (int l = 0; l < Ldim; l++){
        ln_k<<<Mdim, 256>>>(ph, ln1_w + (size_t)l*Cdim, ln1_b + (size_t)l*Cdim, xnh, xnl);

        gemm_tc_k<<<dim3(Mdim/128, C3/128, 1), 256, GT_SMEM>>>(
            xnh, xnl, wqk + (size_t)l*C3*Cdim,
            attn_b + (size_t)l*C3, nullptr, qvh, qvl, C3, Cdim, 4);

        flash_k<<<dim3(Tdim/128, Bdim*Hdim), 256, FA_SMEM>>>(qvh, qvl);

        ln_k<<<Mdim, 256>>>(ph, ln2_w + (size_t)l*Cdim, ln2_b + (size_t)l*Cdim, xnh, xnl);

        gemm_tc_k<<<dim3(Mdim/128, Fdim/128, 1), 256, GT_SMEM>>>(
            xnh, xnl, wf1 + (size_t)l*Fdim*Cdim,
            ff1_b + (size_t)l*Fdim, nullptr, fhh, fhl, Fdim, Cdim, 1);

        // split-K x2: 384 CTAs (fills the resident slots)
        gemm_tc_k<<<dim3(Mdim/128, Cdim/128, 2), 256, GT_SMEM>>>(
            fhh, fhl, wf2 + (size_t)l*Cdim*Fdim,
            ff2_b + (size_t)l*Cdim, ph, nullptr, nullptr, Cdim, Fdim, 2);
    }

    cvt_h_k<<<2048, 256>>>(ph, ah_h, (long)Mdim*Cdim);

    gemm_f16_k<<<dim3(Mdim/128, (Vdim + 127)/128), 256, FH_SMEM>>>(
        ah_h, wlm, logits, Vdim, Cdim);

    loss_row_k<<<Mdim, 256>>>(logits, target);
    if (has_loss)
        loss_reduce_k<<<1, 256>>>(out);
}